// round 15
// baseline (speedup 1.0000x reference)
#include <cuda_runtime.h>
#include <cuda_fp16.h>
#include <math.h>
#include <stdint.h>

#define EMBED   1024
#define NH      8
#define HD      128
#define MAXDIST 128
#define RADIUS_ 256
#define RR      257
#define B_      4
#define S_      1024
#define BHN     32
#define BAND    640

// ---------------- scratch ----------------
__device__ __half g_Qp[BHN * S_ * HD];
__device__ __half g_Kp[BHN * S_ * HD];
__device__ __half g_Vp[BHN * S_ * HD];
__device__ __half g_Wh[3 * EMBED * EMBED];
__device__ __half g_relh[NH * RR * HD];
__device__ __half g_Qrel[BHN * S_ * RR];
__device__ float  g_S[(size_t)BHN * S_ * BAND];
__device__ float2 g_part[BHN * S_ * 5];
__device__ __half g_ctx[B_ * S_ * EMBED];
__device__ __half g_Wop[EMBED * EMBED];

// ---------------- fp16 / mma helpers ----------------
__device__ __forceinline__ uint32_t f2h2(float a, float b) {
    __half2 h = __floats2half2_rn(a, b);
    return *(uint32_t*)&h;
}
__device__ __forceinline__ uint4 pack8(const float4 a, const float4 b) {
    uint4 u;
    u.x = f2h2(a.x, a.y); u.y = f2h2(a.z, a.w);
    u.z = f2h2(b.x, b.y); u.w = f2h2(b.z, b.w);
    return u;
}
__device__ __forceinline__ void mma16(float* d, const uint32_t* a, const uint32_t* b) {
    asm volatile(
        "mma.sync.aligned.m16n8k16.row.col.f32.f16.f16.f32 "
        "{%0,%1,%2,%3}, {%4,%5,%6,%7}, {%8,%9}, {%0,%1,%2,%3};"
        : "+f"(d[0]), "+f"(d[1]), "+f"(d[2]), "+f"(d[3])
        : "r"(a[0]), "r"(a[1]), "r"(a[2]), "r"(a[3]), "r"(b[0]), "r"(b[1]));
}
__device__ __forceinline__ void ldm_x4(uint32_t* d, uint32_t addr) {
    asm volatile("ldmatrix.sync.aligned.m8n8.x4.shared.b16 {%0,%1,%2,%3}, [%4];"
        : "=r"(d[0]), "=r"(d[1]), "=r"(d[2]), "=r"(d[3]) : "r"(addr));
}
__device__ __forceinline__ uint32_t a_lane_off(int lane) {
    return ((lane & 7) + ((lane >> 3) & 1) * 8) * 80 + ((lane >> 4) & 1) * 16;
}
__device__ __forceinline__ uint32_t b_lane_off(int lane) {
    return ((lane & 7) + ((lane >> 4) & 1) * 8) * 80 + ((lane >> 3) & 1) * 16;
}

// ---------------- cp.async helpers ----------------
__device__ __forceinline__ uint32_t smem_u32(const void* p) {
    uint32_t a;
    asm("{ .reg .u64 t; cvta.to.shared.u64 t, %1; cvt.u32.u64 %0, t; }" : "=r"(a) : "l"(p));
    return a;
}
__device__ __forceinline__ void cp16(uint32_t dst, const void* src, bool v) {
    int sz = v ? 16 : 0;
    asm volatile("cp.async.cg.shared.global [%0], [%1], 16, %2;"
                 :: "r"(dst), "l"(src), "r"(sz));
}
#define CP_COMMIT() asm volatile("cp.async.commit_group;" ::: "memory")
#define CP_WAIT1()  asm volatile("cp.async.wait_group 1;" ::: "memory")
#define CP_WAIT0()  asm volatile("cp.async.wait_group 0;" ::: "memory")

// ---------------- fast exp ----------------
__device__ __forceinline__ float fexp(float x) {
    float z = x * 1.4426950408889634f;
    z = fmaxf(z, -127.0f);
    float n = rintf(z);
    float f = z - n;
    float p =           1.3333558e-3f;
    p = fmaf(p, f, 9.6181290e-3f);
    p = fmaf(p, f, 5.5504109e-2f);
    p = fmaf(p, f, 2.4022651e-1f);
    p = fmaf(p, f, 6.9314718e-1f);
    p = fmaf(p, f, 1.0f);
    return p * __int_as_float(((int)n + 127) << 23);
}

// ---------------- scalar fragment slab (128x128 tile) ----------------
__device__ __forceinline__ void mma_slab16(const uint32_t* As, const uint32_t* Bs,
                                           int wm, int wn, int g, int r,
                                           float acc[4][4][4])
{
    #pragma unroll
    for (int ks = 0; ks < 2; ks++) {
        uint32_t af[4][4], bf[4][2];
        #pragma unroll
        for (int i = 0; i < 4; i++) {
            const uint32_t* p = As + (wm * 64 + i * 16 + g) * 20 + ks * 8 + r;
            af[i][0] = p[0]; af[i][1] = p[160]; af[i][2] = p[4]; af[i][3] = p[164];
        }
        #pragma unroll
        for (int j = 0; j < 4; j++) {
            const uint32_t* p = Bs + (wn * 32 + j * 8 + g) * 20 + ks * 8 + r;
            bf[j][0] = p[0]; bf[j][1] = p[4];
        }
        #pragma unroll
        for (int i = 0; i < 4; i++)
            #pragma unroll
            for (int j = 0; j < 4; j++)
                mma16(acc[i][j], af[i], bf[j]);
    }
}

// ---------------- ldmatrix slab (qrel) ----------------
__device__ __forceinline__ void slab_att(uint32_t aaddr, uint32_t baddr, float acc[4][4][4])
{
    #pragma unroll
    for (int ks = 0; ks < 2; ks++) {
        uint32_t af[4][4], bf[4][2], bt[4];
        #pragma unroll
        for (int i = 0; i < 4; i++) ldm_x4(af[i], aaddr + i * 1280 + ks * 32);
        ldm_x4(bt, baddr + ks * 32);
        bf[0][0] = bt[0]; bf[0][1] = bt[1]; bf[1][0] = bt[2]; bf[1][1] = bt[3];
        ldm_x4(bt, baddr + 1280 + ks * 32);
        bf[2][0] = bt[0]; bf[2][1] = bt[1]; bf[3][0] = bt[2]; bf[3][1] = bt[3];
        #pragma unroll
        for (int i = 0; i < 4; i++)
            #pragma unroll
            for (int j = 0; j < 4; j++)
                mma16(acc[i][j], af[i], bf[j]);
    }
}

// ---------------- prep: W -> fp16 ----------------
__global__ void w2h(const float* __restrict__ Wq, const float* __restrict__ Wk,
                    const float* __restrict__ Wv)
{
    const float* W = (blockIdx.y == 0) ? Wq : (blockIdx.y == 1) ? Wk : Wv;
    int i = (blockIdx.x * 256 + threadIdx.x) * 4;
    float4 v = *(const float4*)&W[i];
    *(uint2*)&g_Wh[blockIdx.y * EMBED * EMBED + i] =
        make_uint2(f2h2(v.x, v.y), f2h2(v.z, v.w));
}

// ---------------- proj GEMM: 128x128 tile, 2 CTAs/SM ----------------
__global__ __launch_bounds__(256) void proj3_gemm(
    const float* __restrict__ Q, const float* __restrict__ K, const float* __restrict__ V,
    __half* __restrict__ Qp, __half* __restrict__ Kp, __half* __restrict__ Vp)
{
    __shared__ uint32_t As[2][2560], Bs[2][2560];

    int z = blockIdx.z;
    const float*  A  = (z == 0) ? Q  : (z == 1) ? K  : V;
    const __half* Bm = g_Wh + (size_t)z * EMBED * EMBED;
    __half*       C  = (z == 0) ? Qp : (z == 1) ? Kp : Vp;
    const int m0 = blockIdx.y * 128, n0 = blockIdx.x * 128;

    const int tid = threadIdx.x, lane = tid & 31, wid = tid >> 5;
    const int wm = wid >> 2, wn = wid & 3, g = lane >> 2, r = lane & 3;
    const int lm = tid >> 2, lk8 = (tid & 3) * 8, lw4 = (tid & 3) * 4;

    float acc[4][4][4];
    #pragma unroll
    for (int i = 0; i < 4; i++) for (int j = 0; j < 4; j++) for (int e = 0; e < 4; e++)
        acc[i][j][e] = 0.f;

    float4 pa[4];
    uint4  pb[2];
    auto ldg = [&](int k0) {
        pa[0] = *(const float4*)&A[(size_t)(m0 + lm) * 1024 + k0 + lk8];
        pa[1] = *(const float4*)&A[(size_t)(m0 + lm) * 1024 + k0 + lk8 + 4];
        pa[2] = *(const float4*)&A[(size_t)(m0 + lm + 64) * 1024 + k0 + lk8];
        pa[3] = *(const float4*)&A[(size_t)(m0 + lm + 64) * 1024 + k0 + lk8 + 4];
        pb[0] = *(const uint4*)&Bm[(size_t)(n0 + lm) * 1024 + k0 + lk8];
        pb[1] = *(const uint4*)&Bm[(size_t)(n0 + lm + 64) * 1024 + k0 + lk8];
    };
    auto sts = [&](int buf) {
        *(uint4*)&As[buf][lm * 20 + lw4]        = pack8(pa[0], pa[1]);
        *(uint4*)&As[buf][(lm + 64) * 20 + lw4] = pack8(pa[2], pa[3]);
        *(uint4*)&Bs[buf][lm * 20 + lw4]        = pb[0];
        *(uint4*)&Bs[buf][(lm + 64) * 20 + lw4] = pb[1];
    };

    ldg(0); sts(0); __syncthreads();
    for (int s = 0; s < 32; s++) {
        int cur = s & 1;
        if (s < 31) ldg((s + 1) * 32);
        mma_slab16(As[cur], Bs[cur], wm, wn, g, r, acc);
        if (s < 31) sts(cur ^ 1);
        __syncthreads();
    }

    #pragma unroll
    for (int i = 0; i < 4; i++) {
        int row0 = m0 + wm * 64 + i * 16 + g;
        #pragma unroll
        for (int j = 0; j < 4; j++) {
            int col = n0 + wn * 32 + j * 8 + r * 2;
            int h = col >> 7, d = col & 127;
            #pragma unroll
            for (int half = 0; half < 2; half++) {
                int m = row0 + half * 8;
                int b = m >> 10, ss = m & 1023;
                *(uint32_t*)&C[(((size_t)(b * NH + h)) * S_ + ss) * HD + d] =
                    f2h2(acc[i][j][half * 2], acc[i][j][half * 2 + 1]);
            }
        }
    }
}

// ---------------- out GEMM (R13 exact) ----------------
__global__ __launch_bounds__(256) void out_gemm(
    const __half* __restrict__ A, const __half* __restrict__ Bm, float* __restrict__ C)
{
    extern __shared__ uint32_t sm[];
    uint32_t* AsB = sm;
    uint32_t* BsB = sm + 5120;
    const int m0 = blockIdx.y * 128, n0 = blockIdx.x * 256;

    const int tid = threadIdx.x, lane = tid & 31, wid = tid >> 5;
    const int wm = wid >> 2, wn = wid & 3, g = lane >> 2, r = lane & 3;
    const int lm = tid >> 2, lk8 = (tid & 3) * 8, lw4 = (tid & 3) * 4;

    float acc[4][8][4];
    #pragma unroll
    for (int i = 0; i < 4; i++) for (int j = 0; j < 8; j++) for (int e = 0; e < 4; e++)
        acc[i][j][e] = 0.f;

    auto cpslab = [&](int buf, int k0) {
        uint32_t* As = AsB + buf * 2560;
        uint32_t* Bs = BsB + buf * 5120;
        cp16(smem_u32(&As[lm * 20 + lw4]),        &A[(size_t)(m0 + lm) * 1024 + k0 + lk8], true);
        cp16(smem_u32(&As[(lm + 64) * 20 + lw4]), &A[(size_t)(m0 + lm + 64) * 1024 + k0 + lk8], true);
        #pragma unroll
        for (int p = 0; p < 4; p++)
            cp16(smem_u32(&Bs[(lm + p * 64) * 20 + lw4]),
                 &Bm[(size_t)(n0 + lm + p * 64) * 1024 + k0 + lk8], true);
    };

    cpslab(0, 0); CP_COMMIT();
    for (int s = 0; s < 32; s++) {
        int cur = s & 1;
        if (s < 31) { cpslab(cur ^ 1, (s + 1) * 32); CP_COMMIT(); CP_WAIT1(); }
        else CP_WAIT0();
        __syncthreads();
        const uint32_t* As = AsB + cur * 2560;
        const uint32_t* Bs = BsB + cur * 5120;
        #pragma unroll
        for (int ks = 0; ks < 2; ks++) {
            uint32_t af[4][4], bf[8][2];
            #pragma unroll
            for (int i = 0; i < 4; i++) {
                const uint32_t* p = As + (wm * 64 + i * 16 + g) * 20 + ks * 8 + r;
                af[i][0] = p[0]; af[i][1] = p[160]; af[i][2] = p[4]; af[i][3] = p[164];
            }
            #pragma unroll
            for (int j = 0; j < 8; j++) {
                const uint32_t* p = Bs + (wn * 64 + j * 8 + g) * 20 + ks * 8 + r;
                bf[j][0] = p[0]; bf[j][1] = p[4];
            }
            #pragma unroll
            for (int i = 0; i < 4; i++)
                #pragma unroll
                for (int j = 0; j < 8; j++)
                    mma16(acc[i][j], af[i], bf[j]);
        }
        __syncthreads();
    }

    #pragma unroll
    for (int i = 0; i < 4; i++) {
        int row0 = m0 + wm * 64 + i * 16 + g;
        #pragma unroll
        for (int j = 0; j < 8; j++) {
            int col = n0 + wn * 64 + j * 8 + r * 2;
            *(float2*)&C[(size_t)row0 * 1024 + col]       = make_float2(acc[i][j][0], acc[i][j][1]);
            *(float2*)&C[(size_t)(row0 + 8) * 1024 + col] = make_float2(acc[i][j][2], acc[i][j][3]);
        }
    }
}

// ---------------- prep ----------------
__global__ void wo_permute(const float* __restrict__ Wo)
{
    int n = blockIdx.x;
    for (int f = threadIdx.x; f < 1024; f += 256) {
        int h = f >> 7, d = f & 127;
        g_Wop[n * 1024 + f] = __float2half(Wo[n * 1024 + d * 8 + h]);
    }
}
__global__ void rel2h(const float* __restrict__ rel)
{
    int i = blockIdx.x * 256 + threadIdx.x;
    if (i < NH * RR * HD) g_relh[i] = __float2half(rel[i]);
}

// ---------------- Qrel (R13 exact) ----------------
__global__ __launch_bounds__(256) void tc_qrel()
{
    extern __shared__ uint32_t sm[];
    uint32_t* AsB = sm;
    uint32_t* BsB = sm + 7680;
    const int tid = threadIdx.x, lane = tid & 31, wid = tid >> 5;
    const int wm = wid >> 2, wn = wid & 3, g = lane >> 2, r = lane & 3;
    const int r0 = blockIdx.x * 128, q0 = blockIdx.y * 128, bh = blockIdx.z;
    const int h = bh & 7;
    const __half* Aq = g_Qp + (size_t)bh * S_ * HD;
    const __half* Br = g_relh + (size_t)h * RR * HD;
    const int lm = tid >> 2, lk8 = (tid & 3) * 8, lw4 = (tid & 3) * 4;
    const uint32_t as0 = smem_u32(AsB), bs0 = smem_u32(BsB);
    const uint32_t aoff = wm * 5120 + a_lane_off(lane);
    const uint32_t boff = wn * 2560 + b_lane_off(lane);

    float acc[4][4][4];
    #pragma unroll
    for (int i = 0; i < 4; i++) for (int j = 0; j < 4; j++) for (int e = 0; e < 4; e++) acc[i][j][e] = 0.f;

    auto cpslab = [&](int buf, int k0) {
        uint32_t* As = AsB + buf * 2560;
        uint32_t* Bs = BsB + buf * 2560;
        cp16(smem_u32(&As[lm * 20 + lw4]),        &Aq[(size_t)(q0 + lm) * HD + k0 + lk8], true);
        cp16(smem_u32(&As[(lm + 64) * 20 + lw4]), &Aq[(size_t)(q0 + lm + 64) * HD + k0 + lk8], true);
        #pragma unroll
        for (int p = 0; p < 2; p++) {
            int rg = r0 + lm + p * 64;
            cp16(smem_u32(&Bs[(lm + p * 64) * 20 + lw4]),
                 &Br[(size_t)rg * HD + k0 + lk8], true);
        }
    };

    cpslab(0, 0); CP_COMMIT();
    cpslab(1, 32); CP_COMMIT();
    for (int s = 0; s < 4; s++) {
        if (s == 3) CP_WAIT0(); else CP_WAIT1();
        __syncthreads();
        if (s < 2) { cpslab((s + 2) % 3, (s + 2) * 32); CP_COMMIT(); }
        int cur = s % 3;
        slab_att(as0 + cur * 10240 + aoff, bs0 + cur * 10240 + boff, acc);
    }

    #pragma unroll
    for (int i = 0; i < 4; i++) {
        int row0 = q0 + wm * 64 + i * 16 + g;
        #pragma unroll
        for (int j = 0; j < 4; j++) {
            int col = r0 + wn * 32 + j * 8 + r * 2;
            #pragma unroll
            for (int half = 0; half < 2; half++) {
                size_t base = ((size_t)bh * S_ + row0 + half * 8) * RR;
                g_Qrel[base + col]     = __float2half(acc[i][j][half * 2]);
                g_Qrel[base + col + 1] = __float2half(acc[i][j][half * 2 + 1]);
            }
        }
    }
}

// ---------------- Qrel column 256 ----------------
__global__ __launch_bounds__(256) void qrel_last()
{
    int q  = blockIdx.x * 256 + threadIdx.x;
    int bh = blockIdx.y;
    int h  = bh & 7;
    const uint4* qp = (const uint4*)&g_Qp[((size_t)bh * S_ + q) * HD];
    const uint4* rl = (const uint4*)&g_relh[((size_t)h * RR + 256) * HD];
    float sum = 0.f;
    #pragma unroll
    for (int i = 0; i < 16; i++) {
        uint4 a = qp[i], b = rl[i];
        const __half2* ah = (const __half2*)&a;
        const __half2* bh2 = (const __half2*)&b;
        #pragma unroll
        for (int e = 0; e < 4; e++) {
            float2 fa = __half22float2(ah[e]);
            float2 fb = __half22float2(bh2[e]);
            sum += fa.x * fb.x + fa.y * fb.y;
        }
    }
    g_Qrel[((size_t)bh * S_ + q) * RR + 256] = __float2half(sum);
}

// ---------------- banded scores + partial stats (R13 exact) ----------------
__global__ __launch_bounds__(256) void tc_score(const unsigned char* __restrict__ pad)
{
    __shared__ uint32_t As[2][2560], Bs[2][2560];
    __shared__ float sred[512];
    const int tid = threadIdx.x, lane = tid & 31, wid = tid >> 5;
    const int wm = wid >> 2, wn = wid & 3, g = lane >> 2, r = lane & 3;
    const int kt0 = blockIdx.x * 128, q0 = blockIdx.y * 128, bh = blockIdx.z;
    const int b = bh >> 3;
    const int kbase = q0 - RADIUS_;

    if (kbase + kt0 + 127 < 0 || kbase + kt0 >= S_) {
        float4 ninf = make_float4(-INFINITY, -INFINITY, -INFINITY, -INFINITY);
        #pragma unroll
        for (int p = 0; p < 16; p++) {
            int idx = tid + p * 256;
            int row = idx >> 5, c4 = (idx & 31) * 4;
            *(float4*)&g_S[((size_t)bh * S_ + q0 + row) * BAND + kt0 + c4] = ninf;
        }
        if (tid < 128)
            g_part[((size_t)bh * S_ + q0 + tid) * 5 + blockIdx.x] =
                make_float2(-INFINITY, 0.f);
        return;
    }

    const __half* Aq = g_Qp + (size_t)bh * S_ * HD;
    const __half* Kb = g_Kp + (size_t)bh * S_ * HD;
    const int lm = tid >> 2, lk8 = (tid & 3) * 8, lw4 = (tid & 3) * 4;

    float acc[4][4][4];
    #pragma unroll
    for (int i = 0; i < 4; i++) for (int j = 0; j < 4; j++) for (int e = 0; e < 4; e++) acc[i][j][e] = 0.f;

    auto cpslab = [&](int buf, int k0) {
        cp16(smem_u32(&As[buf][lm * 20 + lw4]),        &Aq[(size_t)(q0 + lm) * HD + k0 + lk8], true);
        cp16(smem_u32(&As[buf][(lm + 64) * 20 + lw4]), &Aq[(size_t)(q0 + lm + 64) * HD + k0 + lk8], true);
        #pragma unroll
        for (int p = 0; p < 2; p++) {
            int k = kbase + kt0 + lm + p * 64;
            int kc = k < 0 ? 0 : (k >= S_ ? S_ - 1 : k);
            cp16(smem_u32(&Bs[buf][(lm + p * 64) * 20 + lw4]),
                 &Kb[(size_t)kc * HD + k0 + lk8], k >= 0 && k < S_);
        }
    };

    cpslab(0, 0); CP_COMMIT();
    for (int s = 0; s < 4; s++) {
        int cur = s & 1;
        if (s < 3) { cpslab(cur ^ 1, (s + 1) * 32); CP_COMMIT(); CP_WAIT1(); }
        else CP_WAIT0();
        __syncthreads();
        mma_slab16(As[cur], Bs[cur], wm, wn, g, r, acc);
        __syncthreads();
    }

    bool okcol[8];
    int  kk_arr[8];
    #pragma unroll
    for (int j = 0; j < 4; j++)
        #pragma unroll
        for (int e = 0; e < 2; e++) {
            int kk = kt0 + wn * 32 + j * 8 + r * 2 + e;
            int k = kbase + kk;
            kk_arr[j * 2 + e] = kk;
            okcol[j * 2 + e] = (k >= 0) && (k < S_) && (pad[b * S_ + (k & 1023)] == 0);
        }

    const float scale = 0.08838834764831845f;
    #pragma unroll
    for (int i = 0; i < 4; i++) {
        #pragma unroll
        for (int half = 0; half < 2; half++) {
            int qg = q0 + wm * 64 + i * 16 + g + half * 8;
            size_t qrow = (size_t)bh * S_ + qg;
            const __half* qr = &g_Qrel[qrow * RR];
            #pragma unroll
            for (int j = 0; j < 4; j++) {
                float v[2];
                #pragma unroll
                for (int e = 0; e < 2; e++) {
                    int kk = kk_arr[j * 2 + e];
                    int k = kbase + kk;
                    int dlt = k - qg;
                    float val = -INFINITY;
                    if (okcol[j * 2 + e] && dlt >= -RADIUS_ && dlt <= RADIUS_) {
                        int rid = dlt < -MAXDIST ? -MAXDIST : (dlt > MAXDIST ? MAXDIST : dlt);
                        rid += MAXDIST;
                        val = (acc[i][j][half * 2 + e] + __half2float(qr[rid])) * scale;
                    }
                    v[e] = val;
                    acc[i][j][half * 2 + e] = val;
                }
                *(float2*)&g_S[qrow * BAND + kk_arr[j * 2]] = make_float2(v[0], v[1]);
            }
        }
    }

    #pragma unroll
    for (int i = 0; i < 4; i++)
        #pragma unroll
        for (int half = 0; half < 2; half++) {
            int rloc = wm * 64 + i * 16 + g + half * 8;
            float tm = -INFINITY;
            #pragma unroll
            for (int j = 0; j < 4; j++) {
                tm = fmaxf(tm, acc[i][j][half * 2]);
                tm = fmaxf(tm, acc[i][j][half * 2 + 1]);
            }
            tm = fmaxf(tm, __shfl_xor_sync(0xffffffffu, tm, 1));
            tm = fmaxf(tm, __shfl_xor_sync(0xffffffffu, tm, 2));
            if (r == 0) sred[rloc * 4 + wn] = tm;
        }
    __syncthreads();
    float Mt[4][2];
    #pragma unroll
    for (int i = 0; i < 4; i++)
        #pragma unroll
        for (int half = 0; half < 2; half++) {
            int rloc = wm * 64 + i * 16 + g + half * 8;
            Mt[i][half] = fmaxf(fmaxf(sred[rloc * 4], sred[rloc * 4 + 1]),
                                fmaxf(sred[rloc * 4 + 2], sred[rloc * 4 + 3]));
        }
    __syncthreads();
    #pragma unroll
    for (int i = 0; i < 4; i++)
        #pragma unroll
        for (int half = 0; half < 2; half++) {
            int rloc = wm * 64 + i * 16 + g + half * 8;
            float ts = 0.f;
            #pragma unroll
            for (int j = 0; j < 4; j++) {
                ts += fexp(acc[i][j][half * 2]     - Mt[i][half]);
                ts += fexp(acc[i][j][half * 2 + 1] - Mt[i][half]);
            }
            ts += __shfl_xor_sync(0xffffffffu, ts, 1);
            ts += __shfl_xor_sync(0xffffffffu, ts, 2);
            if (r == 0) sred[rloc * 4 + wn] = ts;
        }
    __syncthreads();
    if (wn == 0 && r == 0) {
        #pragma unroll
        for (int i = 0; i < 4; i++)
            #pragma unroll
            for (int half = 0; half < 2; half++) {
                int rloc = wm * 64 + i * 16 + g + half * 8;
                float Ssum = sred[rloc * 4] + sred[rloc * 4 + 1] +
                             sred[rloc * 4 + 2] + sred[rloc * 4 + 3];
                g_part[((size_t)bh * S_ + q0 + rloc) * 5 + blockIdx.x] =
                    make_float2(Mt[i][half], Ssum);
            }
    }
}

// ---------------- PV with fused softmax (R13 exact) ----------------
__global__ __launch_bounds__(256) void tc_pv()
{
    __shared__ uint32_t As[2][2560], Bs[2][2560];
    __shared__ float sM[128], sI[128];
    const int tid = threadIdx.x, lane = tid & 31, wid = tid >> 5;
    const int wm = wid >> 2, wn = wid & 3, g = lane >> 2, r = lane & 3;
    const int q0 = blockIdx.x * 128, bh = blockIdx.y;
    const int b = bh >> 3, h = bh & 7;
    const int kbase = q0 - RADIUS_;
    const __half* Vb = g_Vp + (size_t)bh * S_ * HD;
    const float* Sbase = g_S + ((size_t)bh * S_ + q0) * BAND;
    const int lm = tid >> 2, lk8 = (tid & 3) * 8, lw4 = (tid & 3) * 4;
    const int vk2 = (lane & 15) * 2;
    const int vd  = wid * 16 + (lane >> 4) * 4;

    if (tid < 128) {
        const float2* pp = &g_part[((size_t)bh * S_ + q0 + tid) * 5];
        float2 p0 = pp[0], p1 = pp[1], p2 = pp[2], p3 = pp[3], p4 = pp[4];
        float M = fmaxf(fmaxf(fmaxf(p0.x, p1.x), fmaxf(p2.x, p3.x)), p4.x);
        float Ssum = p0.y * fexp(p0.x - M) + p1.y * fexp(p1.x - M) +
                     p2.y * fexp(p2.x - M) + p3.y * fexp(p3.x - M) +
                     p4.y * fexp(p4.x - M);
        sM[tid] = M;
        sI[tid] = 1.f / Ssum;
    }
    __syncthreads();

    const float m0v = sM[lm],      i0v = sI[lm];
    const float m1v = sM[lm + 64], i1v = sI[lm + 64];

    float acc[4][4][4];
    #pragma unroll
    for (int i = 0; i < 4; i++) for (int j = 0; j < 4; j++) for (int e = 0; e < 4; e++) acc[i][j][e] = 0.f;

    float4 pa[4];
    uint2 pe0, pe1, po0, po1;
    auto ldg = [&](int k0) {
        pa[0] = *(const float4*)&Sbase[(size_t)lm * BAND + k0 + lk8];
        pa[1] = *(const float4*)&Sbase[(size_t)lm * BAND + k0 + lk8 + 4];
        pa[2] = *(const float4*)&Sbase[(size_t)(lm + 64) * BAND + k0 + lk8];
        pa[3] = *(const float4*)&Sbase[(size_t)(lm + 64) * BAND + k0 + lk8 + 4];
        int ke = kbase + k0 + vk2;
        int ko = ke + 1;
        bool oke = (ke >= 0 && ke < S_);
        bool oko = (ko >= 0 && ko < S_);
        pe0 = oke ? *(const uint2*)&Vb[(size_t)ke * HD + vd]     : make_uint2(0u, 0u);
        pe1 = oke ? *(const uint2*)&Vb[(size_t)ke * HD + vd + 8] : make_uint2(0u, 0u);
        po0 = oko ? *(const uint2*)&Vb[(size_t)ko * HD + vd]     : make_uint2(0u, 0u);
        po1 = oko ? *(const uint2*)&Vb[(size_t)ko * HD + vd + 8] : make_uint2(0u, 0u);
    };
    auto sts = [&](int buf) {
        float p0[8], p1[8];
        #pragma unroll
        for (int e = 0; e < 4; e++) {
            p0[e]     = fexp((&pa[0].x)[e] - m0v) * i0v;
            p0[e + 4] = fexp((&pa[1].x)[e] - m0v) * i0v;
            p1[e]     = fexp((&pa[2].x)[e] - m1v) * i1v;
            p1[e + 4] = fexp((&pa[3].x)[e] - m1v) * i1v;
        }
        uint4 u0, u1;
        u0.x = f2h2(p0[0], p0[1]); u0.y = f2h2(p0[2], p0[3]);
        u0.z = f2h2(p0[4], p0[5]); u0.w = f2h2(p0[6], p0[7]);
        u1.x = f2h2(p1[0], p1[1]); u1.y = f2h2(p1[2], p1[3]);
        u1.z = f2h2(p1[4], p1[5]); u1.w = f2h2(p1[6], p1[7]);
        *(uint4*)&As[buf][lm * 20 + lw4]        = u0;
        *(uint4*)&As[buf][(lm + 64) * 20 + lw4] = u1;
        int wkk = lane & 15;
        const __half* he0 = (const __half*)&pe0;
        const __half* he1 = (const __half*)&pe1;
        const __half* ho0 = (const __half*)&po0;
        const __half* ho1 = (const __half*)&po1;
        #pragma unroll
        for (int dd = 0; dd < 4; dd++) {
            __half2 w0 = __halves2half2(he0[dd], ho0[dd]);
            __half2 w1 = __halves2half2(he1[dd], ho1[dd]);
            Bs[buf][(vd + dd) * 20 + wkk]     = *(uint32_t*)&w0;
            Bs[buf][(vd + 8 + dd) * 20 + wkk] = *(uint32_t*)&w1;
        }
    };

    ldg(0); sts(0); __syncthreads();
    for (int s = 0; s < 20; s++) {
        int cur = s & 1;
        if (s < 19) ldg((s + 1) * 32);
        mma_slab16(As[cur], Bs[cur], wm, wn, g, r, acc);
        if (s < 19) sts(cur ^ 1);
        __syncthreads();
    }

    #pragma unroll
    for (int i = 0; i < 4; i++) {
        #pragma unroll
        for (int half = 0; half < 2; half++) {
            int q = q0 + wm * 64 + i * 16 + g + half * 8;
            size_t base = ((size_t)(b * S_ + q)) * EMBED + h * HD;
            #pragma unroll
            for (int j = 0; j < 4; j++) {
                int d = wn * 32 + j * 8 + r * 2;
                *(uint32_t*)&g_ctx[base + d] =
                    f2h2(acc[i][j][half * 2], acc[i][j][half * 2 + 1]);
            }
        }
    }
}

// ---------------- launcher ----------------
extern "C" void kernel_launch(void* const* d_in, const int* in_sizes, int n_in,
                              void* d_out, int out_size)
{
    const float*         Q   = (const float*)d_in[0];
    const float*         K   = (const float*)d_in[1];
    const float*         V   = (const float*)d_in[2];
    const unsigned char* pad = (const unsigned char*)d_in[4];
    const float*         Wq  = (const float*)d_in[5];
    const float*         Wk  = (const float*)d_in[6];
    const float*         Wv  = (const float*)d_in[7];
    const float*         Wo  = (const float*)d_in[8];
    const float*         rel = (const float*)d_in[9];
    float*               out = (float*)d_out;

    __half *Qp, *Kp, *Vp, *ctx, *Wop;
    cudaGetSymbolAddress((void**)&Qp,  g_Qp);
    cudaGetSymbolAddress((void**)&Kp,  g_Kp);
    cudaGetSymbolAddress((void**)&Vp,  g_Vp);
    cudaGetSymbolAddress((void**)&ctx, g_ctx);
    cudaGetSymbolAddress((void**)&Wop, g_Wop);

    const int SMEM_W  = (2560 + 5120) * 2 * 4;
    const int SMEM_A3 = (2560 + 2560) * 3 * 4;
    cudaFuncSetAttribute(out_gemm, cudaFuncAttributeMaxDynamicSharedMemorySize, SMEM_W);
    cudaFuncSetAttribute(tc_qrel,  cudaFuncAttributeMaxDynamicSharedMemorySize, SMEM_A3);

    w2h<<<dim3(1024, 3), 256>>>(Wq, Wk, Wv);
    wo_permute<<<1024, 256>>>(Wo);
    rel2h<<<(NH * RR * HD + 255) / 256, 256>>>(rel);

    proj3_gemm<<<dim3(8, 32, 3), 256>>>(Q, K, V, Qp, Kp, Vp);

    tc_qrel<<<dim3(2, 8, 32), 256, SMEM_A3>>>();
    qrel_last<<<dim3(4, 32), 256>>>();
    tc_score<<<dim3(5, 8, 32), 256>>>(pad);
    tc_pv<<<dim3(8, 32), 256>>>();

    out_gemm<<<dim3(4, 32), 256, SMEM_W>>>(ctx, Wop, out);
}

// round 16
// speedup vs baseline: 1.0024x; 1.0024x over previous
#include <cuda_runtime.h>
#include <cuda_fp16.h>
#include <math.h>
#include <stdint.h>

#define EMBED   1024
#define NH      8
#define HD      128
#define MAXDIST 128
#define RADIUS_ 256
#define RR      257
#define B_      4
#define S_      1024
#define BHN     32
#define BAND    640

// ---------------- scratch ----------------
__device__ __half g_Qp[BHN * S_ * HD];
__device__ __half g_Kp[BHN * S_ * HD];
__device__ __half g_Vp[BHN * S_ * HD];
__device__ __half g_Xh[3 * B_ * S_ * EMBED];    // fp16 Q|K|V inputs
__device__ __half g_Wh[3 * EMBED * EMBED];      // fp16 Wq|Wk|Wv
__device__ __half g_relh[NH * RR * HD];
__device__ __half g_Qrel[BHN * S_ * RR];
__device__ float  g_S[(size_t)BHN * S_ * BAND];
__device__ float2 g_part[BHN * S_ * 5];
__device__ __half g_ctx[B_ * S_ * EMBED];
__device__ __half g_Wop[EMBED * EMBED];

// ---------------- fp16 / mma helpers ----------------
__device__ __forceinline__ uint32_t f2h2(float a, float b) {
    __half2 h = __floats2half2_rn(a, b);
    return *(uint32_t*)&h;
}
__device__ __forceinline__ void mma16(float* d, const uint32_t* a, const uint32_t* b) {
    asm volatile(
        "mma.sync.aligned.m16n8k16.row.col.f32.f16.f16.f32 "
        "{%0,%1,%2,%3}, {%4,%5,%6,%7}, {%8,%9}, {%0,%1,%2,%3};"
        : "+f"(d[0]), "+f"(d[1]), "+f"(d[2]), "+f"(d[3])
        : "r"(a[0]), "r"(a[1]), "r"(a[2]), "r"(a[3]), "r"(b[0]), "r"(b[1]));
}
__device__ __forceinline__ void ldm_x4(uint32_t* d, uint32_t addr) {
    asm volatile("ldmatrix.sync.aligned.m8n8.x4.shared.b16 {%0,%1,%2,%3}, [%4];"
        : "=r"(d[0]), "=r"(d[1]), "=r"(d[2]), "=r"(d[3]) : "r"(addr));
}
__device__ __forceinline__ uint32_t a_lane_off(int lane) {
    return ((lane & 7) + ((lane >> 3) & 1) * 8) * 80 + ((lane >> 4) & 1) * 16;
}
__device__ __forceinline__ uint32_t b_lane_off(int lane) {
    return ((lane & 7) + ((lane >> 4) & 1) * 8) * 80 + ((lane >> 3) & 1) * 16;
}

// ---------------- cp.async helpers ----------------
__device__ __forceinline__ uint32_t smem_u32(const void* p) {
    uint32_t a;
    asm("{ .reg .u64 t; cvta.to.shared.u64 t, %1; cvt.u32.u64 %0, t; }" : "=r"(a) : "l"(p));
    return a;
}
__device__ __forceinline__ void cp16(uint32_t dst, const void* src, bool v) {
    int sz = v ? 16 : 0;
    asm volatile("cp.async.cg.shared.global [%0], [%1], 16, %2;"
                 :: "r"(dst), "l"(src), "r"(sz));
}
#define CP_COMMIT() asm volatile("cp.async.commit_group;" ::: "memory")
#define CP_WAIT1()  asm volatile("cp.async.wait_group 1;" ::: "memory")
#define CP_WAIT0()  asm volatile("cp.async.wait_group 0;" ::: "memory")

// ---------------- fast exp ----------------
__device__ __forceinline__ float fexp(float x) {
    float z = x * 1.4426950408889634f;
    z = fmaxf(z, -127.0f);
    float n = rintf(z);
    float f = z - n;
    float p =           1.3333558e-3f;
    p = fmaf(p, f, 9.6181290e-3f);
    p = fmaf(p, f, 5.5504109e-2f);
    p = fmaf(p, f, 2.4022651e-1f);
    p = fmaf(p, f, 6.9314718e-1f);
    p = fmaf(p, f, 1.0f);
    return p * __int_as_float(((int)n + 127) << 23);
}

// ---------------- scalar fragment slabs ----------------
__device__ __forceinline__ void mma_slab16(const uint32_t* As, const uint32_t* Bs,
                                           int wm, int wn, int g, int r,
                                           float acc[4][4][4])
{
    #pragma unroll
    for (int ks = 0; ks < 2; ks++) {
        uint32_t af[4][4], bf[4][2];
        #pragma unroll
        for (int i = 0; i < 4; i++) {
            const uint32_t* p = As + (wm * 64 + i * 16 + g) * 20 + ks * 8 + r;
            af[i][0] = p[0]; af[i][1] = p[160]; af[i][2] = p[4]; af[i][3] = p[164];
        }
        #pragma unroll
        for (int j = 0; j < 4; j++) {
            const uint32_t* p = Bs + (wn * 32 + j * 8 + g) * 20 + ks * 8 + r;
            bf[j][0] = p[0]; bf[j][1] = p[4];
        }
        #pragma unroll
        for (int i = 0; i < 4; i++)
            #pragma unroll
            for (int j = 0; j < 4; j++)
                mma16(acc[i][j], af[i], bf[j]);
    }
}

// wide-tile slab body shared by proj/out (scalar frags, R10-proven)
__device__ __forceinline__ void slab_wide_scalar(const uint32_t* As, const uint32_t* Bs,
                                                 int wm, int wn, int g, int r,
                                                 float acc[4][8][4])
{
    #pragma unroll
    for (int ks = 0; ks < 2; ks++) {
        uint32_t af[4][4], bf[8][2];
        #pragma unroll
        for (int i = 0; i < 4; i++) {
            const uint32_t* p = As + (wm * 64 + i * 16 + g) * 20 + ks * 8 + r;
            af[i][0] = p[0]; af[i][1] = p[160]; af[i][2] = p[4]; af[i][3] = p[164];
        }
        #pragma unroll
        for (int j = 0; j < 8; j++) {
            const uint32_t* p = Bs + (wn * 64 + j * 8 + g) * 20 + ks * 8 + r;
            bf[j][0] = p[0]; bf[j][1] = p[4];
        }
        #pragma unroll
        for (int i = 0; i < 4; i++)
            #pragma unroll
            for (int j = 0; j < 8; j++)
                mma16(acc[i][j], af[i], bf[j]);
    }
}

// ---------------- ldmatrix slab (qrel) ----------------
__device__ __forceinline__ void slab_att(uint32_t aaddr, uint32_t baddr, float acc[4][4][4])
{
    #pragma unroll
    for (int ks = 0; ks < 2; ks++) {
        uint32_t af[4][4], bf[4][2], bt[4];
        #pragma unroll
        for (int i = 0; i < 4; i++) ldm_x4(af[i], aaddr + i * 1280 + ks * 32);
        ldm_x4(bt, baddr + ks * 32);
        bf[0][0] = bt[0]; bf[0][1] = bt[1]; bf[1][0] = bt[2]; bf[1][1] = bt[3];
        ldm_x4(bt, baddr + 1280 + ks * 32);
        bf[2][0] = bt[0]; bf[2][1] = bt[1]; bf[3][0] = bt[2]; bf[3][1] = bt[3];
        #pragma unroll
        for (int i = 0; i < 4; i++)
            #pragma unroll
            for (int j = 0; j < 4; j++)
                mma16(acc[i][j], af[i], bf[j]);
    }
}

// ---------------- prep: inputs & weights -> fp16 ----------------
__global__ void x2h(const float* __restrict__ Q, const float* __restrict__ K,
                    const float* __restrict__ V)
{
    const float* X = (blockIdx.y == 0) ? Q : (blockIdx.y == 1) ? K : V;
    int i = (blockIdx.x * 256 + threadIdx.x) * 4;
    float4 v = *(const float4*)&X[i];
    *(uint2*)&g_Xh[(size_t)blockIdx.y * B_ * S_ * EMBED + i] =
        make_uint2(f2h2(v.x, v.y), f2h2(v.z, v.w));
}
__global__ void w2h(const float* __restrict__ Wq, const float* __restrict__ Wk,
                    const float* __restrict__ Wv)
{
    const float* W = (blockIdx.y == 0) ? Wq : (blockIdx.y == 1) ? Wk : Wv;
    int i = (blockIdx.x * 256 + threadIdx.x) * 4;
    float4 v = *(const float4*)&W[i];
    *(uint2*)&g_Wh[blockIdx.y * EMBED * EMBED + i] =
        make_uint2(f2h2(v.x, v.y), f2h2(v.z, v.w));
}
__global__ void wo_permute(const float* __restrict__ Wo)
{
    int n = blockIdx.x;
    for (int f = threadIdx.x; f < 1024; f += 256) {
        int h = f >> 7, d = f & 127;
        g_Wop[n * 1024 + f] = __float2half(Wo[n * 1024 + d * 8 + h]);
    }
}
__global__ void rel2h(const float* __restrict__ rel)
{
    int i = blockIdx.x * 256 + threadIdx.x;
    if (i < NH * RR * HD) g_relh[i] = __float2half(rel[i]);
}

// ---------------- proj GEMM: fp16 x fp16, wide tile, cp.async (out_gemm clone) ----------------
__global__ __launch_bounds__(256) void proj3_gemm(
    __half* __restrict__ Qp, __half* __restrict__ Kp, __half* __restrict__ Vp)
{
    extern __shared__ uint32_t sm[];
    uint32_t* AsB = sm;
    uint32_t* BsB = sm + 5120;

    int z = blockIdx.z;
    const __half* A  = g_Xh + (size_t)z * B_ * S_ * EMBED;
    const __half* Bm = g_Wh + (size_t)z * EMBED * EMBED;
    __half*       C  = (z == 0) ? Qp : (z == 1) ? Kp : Vp;
    const int m0 = blockIdx.y * 128, n0 = blockIdx.x * 256;

    const int tid = threadIdx.x, lane = tid & 31, wid = tid >> 5;
    const int wm = wid >> 2, wn = wid & 3, g = lane >> 2, r = lane & 3;
    const int lm = tid >> 2, lk8 = (tid & 3) * 8, lw4 = (tid & 3) * 4;

    float acc[4][8][4];
    #pragma unroll
    for (int i = 0; i < 4; i++) for (int j = 0; j < 8; j++) for (int e = 0; e < 4; e++)
        acc[i][j][e] = 0.f;

    auto cpslab = [&](int buf, int k0) {
        uint32_t* As = AsB + buf * 2560;
        uint32_t* Bs = BsB + buf * 5120;
        cp16(smem_u32(&As[lm * 20 + lw4]),        &A[(size_t)(m0 + lm) * 1024 + k0 + lk8], true);
        cp16(smem_u32(&As[(lm + 64) * 20 + lw4]), &A[(size_t)(m0 + lm + 64) * 1024 + k0 + lk8], true);
        #pragma unroll
        for (int p = 0; p < 4; p++)
            cp16(smem_u32(&Bs[(lm + p * 64) * 20 + lw4]),
                 &Bm[(size_t)(n0 + lm + p * 64) * 1024 + k0 + lk8], true);
    };

    cpslab(0, 0); CP_COMMIT();
    for (int s = 0; s < 32; s++) {
        int cur = s & 1;
        if (s < 31) { cpslab(cur ^ 1, (s + 1) * 32); CP_COMMIT(); CP_WAIT1(); }
        else CP_WAIT0();
        __syncthreads();
        slab_wide_scalar(AsB + cur * 2560, BsB + cur * 5120, wm, wn, g, r, acc);
        __syncthreads();
    }

    #pragma unroll
    for (int i = 0; i < 4; i++) {
        int row0 = m0 + wm * 64 + i * 16 + g;
        #pragma unroll
        for (int j = 0; j < 8; j++) {
            int col = n0 + wn * 64 + j * 8 + r * 2;
            int h = col >> 7, d = col & 127;
            #pragma unroll
            for (int half = 0; half < 2; half++) {
                int m = row0 + half * 8;
                int b = m >> 10, ss = m & 1023;
                *(uint32_t*)&C[(((size_t)(b * NH + h)) * S_ + ss) * HD + d] =
                    f2h2(acc[i][j][half * 2], acc[i][j][half * 2 + 1]);
            }
        }
    }
}

// ---------------- out GEMM (R13 exact) ----------------
__global__ __launch_bounds__(256) void out_gemm(
    const __half* __restrict__ A, const __half* __restrict__ Bm, float* __restrict__ C)
{
    extern __shared__ uint32_t sm[];
    uint32_t* AsB = sm;
    uint32_t* BsB = sm + 5120;
    const int m0 = blockIdx.y * 128, n0 = blockIdx.x * 256;

    const int tid = threadIdx.x, lane = tid & 31, wid = tid >> 5;
    const int wm = wid >> 2, wn = wid & 3, g = lane >> 2, r = lane & 3;
    const int lm = tid >> 2, lk8 = (tid & 3) * 8, lw4 = (tid & 3) * 4;

    float acc[4][8][4];
    #pragma unroll
    for (int i = 0; i < 4; i++) for (int j = 0; j < 8; j++) for (int e = 0; e < 4; e++)
        acc[i][j][e] = 0.f;

    auto cpslab = [&](int buf, int k0) {
        uint32_t* As = AsB + buf * 2560;
        uint32_t* Bs = BsB + buf * 5120;
        cp16(smem_u32(&As[lm * 20 + lw4]),        &A[(size_t)(m0 + lm) * 1024 + k0 + lk8], true);
        cp16(smem_u32(&As[(lm + 64) * 20 + lw4]), &A[(size_t)(m0 + lm + 64) * 1024 + k0 + lk8], true);
        #pragma unroll
        for (int p = 0; p < 4; p++)
            cp16(smem_u32(&Bs[(lm + p * 64) * 20 + lw4]),
                 &Bm[(size_t)(n0 + lm + p * 64) * 1024 + k0 + lk8], true);
    };

    cpslab(0, 0); CP_COMMIT();
    for (int s = 0; s < 32; s++) {
        int cur = s & 1;
        if (s < 31) { cpslab(cur ^ 1, (s + 1) * 32); CP_COMMIT(); CP_WAIT1(); }
        else CP_WAIT0();
        __syncthreads();
        slab_wide_scalar(AsB + cur * 2560, BsB + cur * 5120, wm, wn, g, r, acc);
        __syncthreads();
    }

    #pragma unroll
    for (int i = 0; i < 4; i++) {
        int row0 = m0 + wm * 64 + i * 16 + g;
        #pragma unroll
        for (int j = 0; j < 8; j++) {
            int col = n0 + wn * 64 + j * 8 + r * 2;
            *(float2*)&C[(size_t)row0 * 1024 + col]       = make_float2(acc[i][j][0], acc[i][j][1]);
            *(float2*)&C[(size_t)(row0 + 8) * 1024 + col] = make_float2(acc[i][j][2], acc[i][j][3]);
        }
    }
}

// ---------------- Qrel (R13 exact) ----------------
__global__ __launch_bounds__(256) void tc_qrel()
{
    extern __shared__ uint32_t sm[];
    uint32_t* AsB = sm;
    uint32_t* BsB = sm + 7680;
    const int tid = threadIdx.x, lane = tid & 31, wid = tid >> 5;
    const int wm = wid >> 2, wn = wid & 3, g = lane >> 2, r = lane & 3;
    const int r0 = blockIdx.x * 128, q0 = blockIdx.y * 128, bh = blockIdx.z;
    const int h = bh & 7;
    const __half* Aq = g_Qp + (size_t)bh * S_ * HD;
    const __half* Br = g_relh + (size_t)h * RR * HD;
    const int lm = tid >> 2, lk8 = (tid & 3) * 8, lw4 = (tid & 3) * 4;
    const uint32_t as0 = smem_u32(AsB), bs0 = smem_u32(BsB);
    const uint32_t aoff = wm * 5120 + a_lane_off(lane);
    const uint32_t boff = wn * 2560 + b_lane_off(lane);

    float acc[4][4][4];
    #pragma unroll
    for (int i = 0; i < 4; i++) for (int j = 0; j < 4; j++) for (int e = 0; e < 4; e++) acc[i][j][e] = 0.f;

    auto cpslab = [&](int buf, int k0) {
        uint32_t* As = AsB + buf * 2560;
        uint32_t* Bs = BsB + buf * 2560;
        cp16(smem_u32(&As[lm * 20 + lw4]),        &Aq[(size_t)(q0 + lm) * HD + k0 + lk8], true);
        cp16(smem_u32(&As[(lm + 64) * 20 + lw4]), &Aq[(size_t)(q0 + lm + 64) * HD + k0 + lk8], true);
        #pragma unroll
        for (int p = 0; p < 2; p++) {
            int rg = r0 + lm + p * 64;
            cp16(smem_u32(&Bs[(lm + p * 64) * 20 + lw4]),
                 &Br[(size_t)rg * HD + k0 + lk8], true);
        }
    };

    cpslab(0, 0); CP_COMMIT();
    cpslab(1, 32); CP_COMMIT();
    for (int s = 0; s < 4; s++) {
        if (s == 3) CP_WAIT0(); else CP_WAIT1();
        __syncthreads();
        if (s < 2) { cpslab((s + 2) % 3, (s + 2) * 32); CP_COMMIT(); }
        int cur = s % 3;
        slab_att(as0 + cur * 10240 + aoff, bs0 + cur * 10240 + boff, acc);
    }

    #pragma unroll
    for (int i = 0; i < 4; i++) {
        int row0 = q0 + wm * 64 + i * 16 + g;
        #pragma unroll
        for (int j = 0; j < 4; j++) {
            int col = r0 + wn * 32 + j * 8 + r * 2;
            #pragma unroll
            for (int half = 0; half < 2; half++) {
                size_t base = ((size_t)bh * S_ + row0 + half * 8) * RR;
                g_Qrel[base + col]     = __float2half(acc[i][j][half * 2]);
                g_Qrel[base + col + 1] = __float2half(acc[i][j][half * 2 + 1]);
            }
        }
    }
}

// ---------------- Qrel column 256 ----------------
__global__ __launch_bounds__(256) void qrel_last()
{
    int q  = blockIdx.x * 256 + threadIdx.x;
    int bh = blockIdx.y;
    int h  = bh & 7;
    const uint4* qp = (const uint4*)&g_Qp[((size_t)bh * S_ + q) * HD];
    const uint4* rl = (const uint4*)&g_relh[((size_t)h * RR + 256) * HD];
    float sum = 0.f;
    #pragma unroll
    for (int i = 0; i < 16; i++) {
        uint4 a = qp[i], b = rl[i];
        const __half2* ah = (const __half2*)&a;
        const __half2* bh2 = (const __half2*)&b;
        #pragma unroll
        for (int e = 0; e < 4; e++) {
            float2 fa = __half22float2(ah[e]);
            float2 fb = __half22float2(bh2[e]);
            sum += fa.x * fb.x + fa.y * fb.y;
        }
    }
    g_Qrel[((size_t)bh * S_ + q) * RR + 256] = __float2half(sum);
}

// ---------------- banded scores + partial stats (R13 exact) ----------------
__global__ __launch_bounds__(256) void tc_score(const unsigned char* __restrict__ pad)
{
    __shared__ uint32_t As[2][2560], Bs[2][2560];
    __shared__ float sred[512];
    const int tid = threadIdx.x, lane = tid & 31, wid = tid >> 5;
    const int wm = wid >> 2, wn = wid & 3, g = lane >> 2, r = lane & 3;
    const int kt0 = blockIdx.x * 128, q0 = blockIdx.y * 128, bh = blockIdx.z;
    const int b = bh >> 3;
    const int kbase = q0 - RADIUS_;

    if (kbase + kt0 + 127 < 0 || kbase + kt0 >= S_) {
        float4 ninf = make_float4(-INFINITY, -INFINITY, -INFINITY, -INFINITY);
        #pragma unroll
        for (int p = 0; p < 16; p++) {
            int idx = tid + p * 256;
            int row = idx >> 5, c4 = (idx & 31) * 4;
            *(float4*)&g_S[((size_t)bh * S_ + q0 + row) * BAND + kt0 + c4] = ninf;
        }
        if (tid < 128)
            g_part[((size_t)bh * S_ + q0 + tid) * 5 + blockIdx.x] =
                make_float2(-INFINITY, 0.f);
        return;
    }

    const __half* Aq = g_Qp + (size_t)bh * S_ * HD;
    const __half* Kb = g_Kp + (size_t)bh * S_ * HD;
    const int lm = tid >> 2, lk8 = (tid & 3) * 8, lw4 = (tid & 3) * 4;

    float acc[4][4][4];
    #pragma unroll
    for (int i = 0; i < 4; i++) for (int j = 0; j < 4; j++) for (int e = 0; e < 4; e++) acc[i][j][e] = 0.f;

    auto cpslab = [&](int buf, int k0) {
        cp16(smem_u32(&As[buf][lm * 20 + lw4]),        &Aq[(size_t)(q0 + lm) * HD + k0 + lk8], true);
        cp16(smem_u32(&As[buf][(lm + 64) * 20 + lw4]), &Aq[(size_t)(q0 + lm + 64) * HD + k0 + lk8], true);
        #pragma unroll
        for (int p = 0; p < 2; p++) {
            int k = kbase + kt0 + lm + p * 64;
            int kc = k < 0 ? 0 : (k >= S_ ? S_ - 1 : k);
            cp16(smem_u32(&Bs[buf][(lm + p * 64) * 20 + lw4]),
                 &Kb[(size_t)kc * HD + k0 + lk8], k >= 0 && k < S_);
        }
    };

    cpslab(0, 0); CP_COMMIT();
    for (int s = 0; s < 4; s++) {
        int cur = s & 1;
        if (s < 3) { cpslab(cur ^ 1, (s + 1) * 32); CP_COMMIT(); CP_WAIT1(); }
        else CP_WAIT0();
        __syncthreads();
        mma_slab16(As[cur], Bs[cur], wm, wn, g, r, acc);
        __syncthreads();
    }

    bool okcol[8];
    int  kk_arr[8];
    #pragma unroll
    for (int j = 0; j < 4; j++)
        #pragma unroll
        for (int e = 0; e < 2; e++) {
            int kk = kt0 + wn * 32 + j * 8 + r * 2 + e;
            int k = kbase + kk;
            kk_arr[j * 2 + e] = kk;
            okcol[j * 2 + e] = (k >= 0) && (k < S_) && (pad[b * S_ + (k & 1023)] == 0);
        }

    const float scale = 0.08838834764831845f;
    #pragma unroll
    for (int i = 0; i < 4; i++) {
        #pragma unroll
        for (int half = 0; half < 2; half++) {
            int qg = q0 + wm * 64 + i * 16 + g + half * 8;
            size_t qrow = (size_t)bh * S_ + qg;
            const __half* qr = &g_Qrel[qrow * RR];
            #pragma unroll
            for (int j = 0; j < 4; j++) {
                float v[2];
                #pragma unroll
                for (int e = 0; e < 2; e++) {
                    int kk = kk_arr[j * 2 + e];
                    int k = kbase + kk;
                    int dlt = k - qg;
                    float val = -INFINITY;
                    if (okcol[j * 2 + e] && dlt >= -RADIUS_ && dlt <= RADIUS_) {
                        int rid = dlt < -MAXDIST ? -MAXDIST : (dlt > MAXDIST ? MAXDIST : dlt);
                        rid += MAXDIST;
                        val = (acc[i][j][half * 2 + e] + __half2float(qr[rid])) * scale;
                    }
                    v[e] = val;
                    acc[i][j][half * 2 + e] = val;
                }
                *(float2*)&g_S[qrow * BAND + kk_arr[j * 2]] = make_float2(v[0], v[1]);
            }
        }
    }

    #pragma unroll
    for (int i = 0; i < 4; i++)
        #pragma unroll
        for (int half = 0; half < 2; half++) {
            int rloc = wm * 64 + i * 16 + g + half * 8;
            float tm = -INFINITY;
            #pragma unroll
            for (int j = 0; j < 4; j++) {
                tm = fmaxf(tm, acc[i][j][half * 2]);
                tm = fmaxf(tm, acc[i][j][half * 2 + 1]);
            }
            tm = fmaxf(tm, __shfl_xor_sync(0xffffffffu, tm, 1));
            tm = fmaxf(tm, __shfl_xor_sync(0xffffffffu, tm, 2));
            if (r == 0) sred[rloc * 4 + wn] = tm;
        }
    __syncthreads();
    float Mt[4][2];
    #pragma unroll
    for (int i = 0; i < 4; i++)
        #pragma unroll
        for (int half = 0; half < 2; half++) {
            int rloc = wm * 64 + i * 16 + g + half * 8;
            Mt[i][half] = fmaxf(fmaxf(sred[rloc * 4], sred[rloc * 4 + 1]),
                                fmaxf(sred[rloc * 4 + 2], sred[rloc * 4 + 3]));
        }
    __syncthreads();
    #pragma unroll
    for (int i = 0; i < 4; i++)
        #pragma unroll
        for (int half = 0; half < 2; half++) {
            int rloc = wm * 64 + i * 16 + g + half * 8;
            float ts = 0.f;
            #pragma unroll
            for (int j = 0; j < 4; j++) {
                ts += fexp(acc[i][j][half * 2]     - Mt[i][half]);
                ts += fexp(acc[i][j][half * 2 + 1] - Mt[i][half]);
            }
            ts += __shfl_xor_sync(0xffffffffu, ts, 1);
            ts += __shfl_xor_sync(0xffffffffu, ts, 2);
            if (r == 0) sred[rloc * 4 + wn] = ts;
        }
    __syncthreads();
    if (wn == 0 && r == 0) {
        #pragma unroll
        for (int i = 0; i < 4; i++)
            #pragma unroll
            for (int half = 0; half < 2; half++) {
                int rloc = wm * 64 + i * 16 + g + half * 8;
                float Ssum = sred[rloc * 4] + sred[rloc * 4 + 1] +
                             sred[rloc * 4 + 2] + sred[rloc * 4 + 3];
                g_part[((size_t)bh * S_ + q0 + rloc) * 5 + blockIdx.x] =
                    make_float2(Mt[i][half], Ssum);
            }
    }
}

// ---------------- PV with fused softmax (R13 exact) ----------------
__global__ __launch_bounds__(256) void tc_pv()
{
    __shared__ uint32_t As[2][2560], Bs[2][2560];
    __shared__ float sM[128], sI[128];
    const int tid = threadIdx.x, lane = tid & 31, wid = tid >> 5;
    const int wm = wid >> 2, wn = wid & 3, g = lane >> 2, r = lane & 3;
    const int q0 = blockIdx.x * 128, bh = blockIdx.y;
    const int b = bh >> 3, h = bh & 7;
    const int kbase = q0 - RADIUS_;
    const __half* Vb = g_Vp + (size_t)bh * S_ * HD;
    const float* Sbase = g_S + ((size_t)bh * S_ + q0) * BAND;
    const int lm = tid >> 2, lk8 = (tid & 3) * 8, lw4 = (tid & 3) * 4;
    const int vk2 = (lane & 15) * 2;
    const int vd  = wid * 16 + (lane >> 4) * 4;

    if (tid < 128) {
        const float2* pp = &g_part[((size_t)bh * S_ + q0 + tid) * 5];
        float2 p0 = pp[0], p1 = pp[1], p2 = pp[2], p3 = pp[3], p4 = pp[4];
        float M = fmaxf(fmaxf(fmaxf(p0.x, p1.x), fmaxf(p2.x, p3.x)), p4.x);
        float Ssum = p0.y * fexp(p0.x - M) + p1.y * fexp(p1.x - M) +
                     p2.y * fexp(p2.x - M) + p3.y * fexp(p3.x - M) +
                     p4.y * fexp(p4.x - M);
        sM[tid] = M;
        sI[tid] = 1.f / Ssum;
    }
    __syncthreads();

    const float m0v = sM[lm],      i0v = sI[lm];
    const float m1v = sM[lm + 64], i1v = sI[lm + 64];

    float acc[4][4][4];
    #pragma unroll
    for (int i = 0; i < 4; i++) for (int j = 0; j < 4; j++) for (int e = 0; e < 4; e++) acc[i][j][e] = 0.f;

    float4 pa[4];
    uint2 pe0, pe1, po0, po1;
    auto ldg = [&](int k0) {
        pa[0] = *(const float4*)&Sbase[(size_t)lm * BAND + k0 + lk8];
        pa[1] = *(const float4*)&Sbase[(size_t)lm * BAND + k0 + lk8 + 4];
        pa[2] = *(const float4*)&Sbase[(size_t)(lm + 64) * BAND + k0 + lk8];
        pa[3] = *(const float4*)&Sbase[(size_t)(lm + 64) * BAND + k0 + lk8 + 4];
        int ke = kbase + k0 + vk2;
        int ko = ke + 1;
        bool oke = (ke >= 0 && ke < S_);
        bool oko = (ko >= 0 && ko < S_);
        pe0 = oke ? *(const uint2*)&Vb[(size_t)ke * HD + vd]     : make_uint2(0u, 0u);
        pe1 = oke ? *(const uint2*)&Vb[(size_t)ke * HD + vd + 8] : make_uint2(0u, 0u);
        po0 = oko ? *(const uint2*)&Vb[(size_t)ko * HD + vd]     : make_uint2(0u, 0u);
        po1 = oko ? *(const uint2*)&Vb[(size_t)ko * HD + vd + 8] : make_uint2(0u, 0u);
    };
    auto sts = [&](int buf) {
        float p0[8], p1[8];
        #pragma unroll
        for (int e = 0; e < 4; e++) {
            p0[e]     = fexp((&pa[0].x)[e] - m0v) * i0v;
            p0[e + 4] = fexp((&pa[1].x)[e] - m0v) * i0v;
            p1[e]     = fexp((&pa[2].x)[e] - m1v) * i1v;
            p1[e + 4] = fexp((&pa[3].x)[e] - m1v) * i1v;
        }
        uint4 u0, u1;
        u0.x = f2h2(p0[0], p0[1]); u0.y = f2h2(p0[2], p0[3]);
        u0.z = f2h2(p0[4], p0[5]); u0.w = f2h2(p0[6], p0[7]);
        u1.x = f2h2(p1[0], p1[1]); u1.y = f2h2(p1[2], p1[3]);
        u1.z = f2h2(p1[4], p1[5]); u1.w = f2h2(p1[6], p1[7]);
        *(uint4*)&As[buf][lm * 20 + lw4]        = u0;
        *(uint4*)&As[buf][(lm + 64) * 20 + lw4] = u1;
        int wkk = lane & 15;
        const __half* he0 = (const __half*)&pe0;
        const __half* he1 = (const __half*)&pe1;
        const __half* ho0 = (const __half*)&po0;
        const __half* ho1 = (const __half*)&po1;
        #pragma unroll
        for (int dd = 0; dd < 4; dd++) {
            __half2 w0 = __halves2half2(he0[dd], ho0[dd]);
            __half2 w1 = __halves2half2(he1[dd], ho1[dd]);
            Bs[buf][(vd + dd) * 20 + wkk]     = *(uint32_t*)&w0;
            Bs[buf][(vd + 8 + dd) * 20 + wkk] = *(uint32_t*)&w1;
        }
    };

    ldg(0); sts(0); __syncthreads();
    for (int s = 0; s < 20; s++) {
        int cur = s & 1;
        if (s < 19) ldg((s + 1) * 32);
        mma_slab16(As[cur], Bs[cur], wm, wn, g, r, acc);
        if (s < 19) sts(cur ^ 1);
        __syncthreads();
    }

    #pragma unroll
    for (int i = 0; i < 4; i++) {
        #pragma unroll
        for (int half = 0; half < 2; half++) {
            int q = q0 + wm * 64 + i * 16 + g + half * 8;
            size_t base = ((size_t)(b * S_ + q)) * EMBED + h * HD;
            #pragma unroll
            for (int j = 0; j < 4; j++) {
                int d = wn * 32 + j * 8 + r * 2;
                *(uint32_t*)&g_ctx[base + d] =
                    f2h2(acc[i][j][half * 2], acc[i][j][half * 2 + 1]);
            }
        }
    }
}

// ---------------- launcher ----------------
extern "C" void kernel_launch(void* const* d_in, const int* in_sizes, int n_in,
                              void* d_out, int out_size)
{
    const float*         Q   = (const float*)d_in[0];
    const float*         K   = (const float*)d_in[1];
    const float*         V   = (const float*)d_in[2];
    const unsigned char* pad = (const unsigned char*)d_in[4];
    const float*         Wq  = (const float*)d_in[5];
    const float*         Wk  = (const float*)d_in[6];
    const float*         Wv  = (const float*)d_in[7];
    const float*         Wo  = (const float*)d_in[8];
    const float*         rel = (const float*)d_in[9];
    float*               out = (float*)d_out;

    __half *Qp, *Kp, *Vp, *ctx, *Wop;
    cudaGetSymbolAddress((void**)&Qp,  g_Qp);
    cudaGetSymbolAddress((void**)&Kp,  g_Kp);
    cudaGetSymbolAddress((void**)&Vp,  g_Vp);
    cudaGetSymbolAddress((void**)&ctx, g_ctx);
    cudaGetSymbolAddress((void**)&Wop, g_Wop);

    const int SMEM_W  = (2560 + 5120) * 2 * 4;
    const int SMEM_A3 = (2560 + 2560) * 3 * 4;
    cudaFuncSetAttribute(proj3_gemm, cudaFuncAttributeMaxDynamicSharedMemorySize, SMEM_W);
    cudaFuncSetAttribute(out_gemm,   cudaFuncAttributeMaxDynamicSharedMemorySize, SMEM_W);
    cudaFuncSetAttribute(tc_qrel,    cudaFuncAttributeMaxDynamicSharedMemorySize, SMEM_A3);

    x2h<<<dim3(4096, 3), 256>>>(Q, K, V);
    w2h<<<dim3(1024, 3), 256>>>(Wq, Wk, Wv);
    wo_permute<<<1024, 256>>>(Wo);
    rel2h<<<(NH * RR * HD + 255) / 256, 256>>>(rel);

    proj3_gemm<<<dim3(4, 32, 3), 256, SMEM_W>>>(Qp, Kp, Vp);

    tc_qrel<<<dim3(2, 8, 32), 256, SMEM_A3>>>();
    qrel_last<<<dim3(4, 32), 256>>>();
    tc_score<<<dim3(5, 8, 32), 256>>>(pad);
    tc_pv<<<dim3(8, 32), 256>>>();

    out_gemm<<<dim3(4, 32), 256, SMEM_W>>>(ctx, Wop, out);
}

// round 17
// speedup vs baseline: 1.0687x; 1.0661x over previous
#include <cuda_runtime.h>
#include <cuda_fp16.h>
#include <math.h>
#include <stdint.h>

#define EMBED   1024
#define NH      8
#define HD      128
#define MAXDIST 128
#define RADIUS_ 256
#define RR      257
#define B_      4
#define S_      1024
#define BHN     32
#define BAND    640

// ---------------- scratch ----------------
__device__ __half g_Qp[BHN * S_ * HD];
__device__ __half g_Kp[BHN * S_ * HD];
__device__ __half g_Vp[BHN * S_ * HD];
__device__ __half g_relh[NH * RR * HD];
__device__ __half g_Qrel[BHN * S_ * RR];
__device__ __half g_S[(size_t)BHN * S_ * BAND];   // fp16 tile-partial probabilities
__device__ float2 g_part[BHN * S_ * 5];           // per (row, ktile): (max, sumexp)
__device__ __half g_ctx[B_ * S_ * EMBED];
__device__ __half g_Wop[EMBED * EMBED];

// ---------------- fp16 / mma helpers ----------------
__device__ __forceinline__ uint32_t f2h2(float a, float b) {
    __half2 h = __floats2half2_rn(a, b);
    return *(uint32_t*)&h;
}
__device__ __forceinline__ uint4 pack8(const float4 a, const float4 b) {
    uint4 u;
    u.x = f2h2(a.x, a.y); u.y = f2h2(a.z, a.w);
    u.z = f2h2(b.x, b.y); u.w = f2h2(b.z, b.w);
    return u;
}
__device__ __forceinline__ void mma16(float* d, const uint32_t* a, const uint32_t* b) {
    asm volatile(
        "mma.sync.aligned.m16n8k16.row.col.f32.f16.f16.f32 "
        "{%0,%1,%2,%3}, {%4,%5,%6,%7}, {%8,%9}, {%0,%1,%2,%3};"
        : "+f"(d[0]), "+f"(d[1]), "+f"(d[2]), "+f"(d[3])
        : "r"(a[0]), "r"(a[1]), "r"(a[2]), "r"(a[3]), "r"(b[0]), "r"(b[1]));
}
__device__ __forceinline__ void ldm_x4(uint32_t* d, uint32_t addr) {
    asm volatile("ldmatrix.sync.aligned.m8n8.x4.shared.b16 {%0,%1,%2,%3}, [%4];"
        : "=r"(d[0]), "=r"(d[1]), "=r"(d[2]), "=r"(d[3]) : "r"(addr));
}
__device__ __forceinline__ uint32_t a_lane_off(int lane) {
    return ((lane & 7) + ((lane >> 3) & 1) * 8) * 80 + ((lane >> 4) & 1) * 16;
}
__device__ __forceinline__ uint32_t b_lane_off(int lane) {
    return ((lane & 7) + ((lane >> 4) & 1) * 8) * 80 + ((lane >> 3) & 1) * 16;
}

// ---------------- cp.async helpers ----------------
__device__ __forceinline__ uint32_t smem_u32(const void* p) {
    uint32_t a;
    asm("{ .reg .u64 t; cvta.to.shared.u64 t, %1; cvt.u32.u64 %0, t; }" : "=r"(a) : "l"(p));
    return a;
}
__device__ __forceinline__ void cp16(uint32_t dst, const void* src, bool v) {
    int sz = v ? 16 : 0;
    asm volatile("cp.async.cg.shared.global [%0], [%1], 16, %2;"
                 :: "r"(dst), "l"(src), "r"(sz));
}
#define CP_COMMIT() asm volatile("cp.async.commit_group;" ::: "memory")
#define CP_WAIT1()  asm volatile("cp.async.wait_group 1;" ::: "memory")
#define CP_WAIT0()  asm volatile("cp.async.wait_group 0;" ::: "memory")

// ---------------- fast exp (x <= 0, -inf -> exactly 0) ----------------
__device__ __forceinline__ float fexp(float x) {
    float z = x * 1.4426950408889634f;
    z = fmaxf(z, -127.0f);
    float n = rintf(z);
    float f = z - n;
    float p =           1.3333558e-3f;
    p = fmaf(p, f, 9.6181290e-3f);
    p = fmaf(p, f, 5.5504109e-2f);
    p = fmaf(p, f, 2.4022651e-1f);
    p = fmaf(p, f, 6.9314718e-1f);
    p = fmaf(p, f, 1.0f);
    return p * __int_as_float(((int)n + 127) << 23);
}

// ---------------- scalar fragment slab (128x128 tile) ----------------
__device__ __forceinline__ void mma_slab16(const uint32_t* As, const uint32_t* Bs,
                                           int wm, int wn, int g, int r,
                                           float acc[4][4][4])
{
    #pragma unroll
    for (int ks = 0; ks < 2; ks++) {
        uint32_t af[4][4], bf[4][2];
        #pragma unroll
        for (int i = 0; i < 4; i++) {
            const uint32_t* p = As + (wm * 64 + i * 16 + g) * 20 + ks * 8 + r;
            af[i][0] = p[0]; af[i][1] = p[160]; af[i][2] = p[4]; af[i][3] = p[164];
        }
        #pragma unroll
        for (int j = 0; j < 4; j++) {
            const uint32_t* p = Bs + (wn * 32 + j * 8 + g) * 20 + ks * 8 + r;
            bf[j][0] = p[0]; bf[j][1] = p[4];
        }
        #pragma unroll
        for (int i = 0; i < 4; i++)
            #pragma unroll
            for (int j = 0; j < 4; j++)
                mma16(acc[i][j], af[i], bf[j]);
    }
}

// ---------------- ldmatrix slab (qrel) ----------------
__device__ __forceinline__ void slab_att(uint32_t aaddr, uint32_t baddr, float acc[4][4][4])
{
    #pragma unroll
    for (int ks = 0; ks < 2; ks++) {
        uint32_t af[4][4], bf[4][2], bt[4];
        #pragma unroll
        for (int i = 0; i < 4; i++) ldm_x4(af[i], aaddr + i * 1280 + ks * 32);
        ldm_x4(bt, baddr + ks * 32);
        bf[0][0] = bt[0]; bf[0][1] = bt[1]; bf[1][0] = bt[2]; bf[1][1] = bt[3];
        ldm_x4(bt, baddr + 1280 + ks * 32);
        bf[2][0] = bt[0]; bf[2][1] = bt[1]; bf[3][0] = bt[2]; bf[3][1] = bt[3];
        #pragma unroll
        for (int i = 0; i < 4; i++)
            #pragma unroll
            for (int j = 0; j < 4; j++)
                mma16(acc[i][j], af[i], bf[j]);
    }
}

// ---------------- proj GEMM (R13-best exact: fp32 A, fp32 W, wide tile) ----------------
__global__ __launch_bounds__(256) void proj3_gemm(
    const float* __restrict__ Q, const float* __restrict__ K, const float* __restrict__ V,
    const float* __restrict__ Wq, const float* __restrict__ Wk, const float* __restrict__ Wv,
    __half* __restrict__ Qp, __half* __restrict__ Kp, __half* __restrict__ Vp)
{
    extern __shared__ uint32_t sm[];
    uint32_t* AsB = sm;
    uint32_t* BsB = sm + 5120;

    int z = blockIdx.z;
    const float* A  = (z == 0) ? Q  : (z == 1) ? K  : V;
    const float* Bm = (z == 0) ? Wq : (z == 1) ? Wk : Wv;
    __half*      C  = (z == 0) ? Qp : (z == 1) ? Kp : Vp;
    const int m0 = blockIdx.y * 128, n0 = blockIdx.x * 256;

    const int tid = threadIdx.x, lane = tid & 31, wid = tid >> 5;
    const int wm = wid >> 2, wn = wid & 3, g = lane >> 2, r = lane & 3;
    const int lm = tid >> 2, lk8 = (tid & 3) * 8, lw4 = (tid & 3) * 4;

    float acc[4][8][4];
    #pragma unroll
    for (int i = 0; i < 4; i++) for (int j = 0; j < 8; j++) for (int e = 0; e < 4; e++)
        acc[i][j][e] = 0.f;

    float4 pa[4], pb[8];
    auto ldg = [&](int k0) {
        pa[0] = *(const float4*)&A[(size_t)(m0 + lm) * 1024 + k0 + lk8];
        pa[1] = *(const float4*)&A[(size_t)(m0 + lm) * 1024 + k0 + lk8 + 4];
        pa[2] = *(const float4*)&A[(size_t)(m0 + lm + 64) * 1024 + k0 + lk8];
        pa[3] = *(const float4*)&A[(size_t)(m0 + lm + 64) * 1024 + k0 + lk8 + 4];
        #pragma unroll
        for (int p = 0; p < 4; p++) {
            pb[2 * p]     = *(const float4*)&Bm[(size_t)(n0 + lm + p * 64) * 1024 + k0 + lk8];
            pb[2 * p + 1] = *(const float4*)&Bm[(size_t)(n0 + lm + p * 64) * 1024 + k0 + lk8 + 4];
        }
    };
    auto sts = [&](int buf) {
        uint32_t* As = AsB + buf * 2560;
        uint32_t* Bs = BsB + buf * 5120;
        *(uint4*)&As[lm * 20 + lw4]        = pack8(pa[0], pa[1]);
        *(uint4*)&As[(lm + 64) * 20 + lw4] = pack8(pa[2], pa[3]);
        #pragma unroll
        for (int p = 0; p < 4; p++)
            *(uint4*)&Bs[(lm + p * 64) * 20 + lw4] = pack8(pb[2 * p], pb[2 * p + 1]);
    };

    ldg(0); sts(0); __syncthreads();
    for (int s = 0; s < 32; s++) {
        int cur = s & 1;
        if (s < 31) ldg((s + 1) * 32);
        const uint32_t* As = AsB + cur * 2560;
        const uint32_t* Bs = BsB + cur * 5120;
        #pragma unroll
        for (int ks = 0; ks < 2; ks++) {
            uint32_t af[4][4], bf[8][2];
            #pragma unroll
            for (int i = 0; i < 4; i++) {
                const uint32_t* p = As + (wm * 64 + i * 16 + g) * 20 + ks * 8 + r;
                af[i][0] = p[0]; af[i][1] = p[160]; af[i][2] = p[4]; af[i][3] = p[164];
            }
            #pragma unroll
            for (int j = 0; j < 8; j++) {
                const uint32_t* p = Bs + (wn * 64 + j * 8 + g) * 20 + ks * 8 + r;
                bf[j][0] = p[0]; bf[j][1] = p[4];
            }
            #pragma unroll
            for (int i = 0; i < 4; i++)
                #pragma unroll
                for (int j = 0; j < 8; j++)
                    mma16(acc[i][j], af[i], bf[j]);
        }
        if (s < 31) sts(cur ^ 1);
        __syncthreads();
    }

    #pragma unroll
    for (int i = 0; i < 4; i++) {
        int row0 = m0 + wm * 64 + i * 16 + g;
        #pragma unroll
        for (int j = 0; j < 8; j++) {
            int col = n0 + wn * 64 + j * 8 + r * 2;
            int h = col >> 7, d = col & 127;
            #pragma unroll
            for (int half = 0; half < 2; half++) {
                int m = row0 + half * 8;
                int b = m >> 10, ss = m & 1023;
                *(uint32_t*)&C[(((size_t)(b * NH + h)) * S_ + ss) * HD + d] =
                    f2h2(acc[i][j][half * 2], acc[i][j][half * 2 + 1]);
            }
        }
    }
}

// ---------------- out GEMM (R13-best exact) ----------------
__global__ __launch_bounds__(256) void out_gemm(
    const __half* __restrict__ A, const __half* __restrict__ Bm, float* __restrict__ C)
{
    extern __shared__ uint32_t sm[];
    uint32_t* AsB = sm;
    uint32_t* BsB = sm + 5120;
    const int m0 = blockIdx.y * 128, n0 = blockIdx.x * 256;

    const int tid = threadIdx.x, lane = tid & 31, wid = tid >> 5;
    const int wm = wid >> 2, wn = wid & 3, g = lane >> 2, r = lane & 3;
    const int lm = tid >> 2, lk8 = (tid & 3) * 8, lw4 = (tid & 3) * 4;

    float acc[4][8][4];
    #pragma unroll
    for (int i = 0; i < 4; i++) for (int j = 0; j < 8; j++) for (int e = 0; e < 4; e++)
        acc[i][j][e] = 0.f;

    auto cpslab = [&](int buf, int k0) {
        uint32_t* As = AsB + buf * 2560;
        uint32_t* Bs = BsB + buf * 5120;
        cp16(smem_u32(&As[lm * 20 + lw4]),        &A[(size_t)(m0 + lm) * 1024 + k0 + lk8], true);
        cp16(smem_u32(&As[(lm + 64) * 20 + lw4]), &A[(size_t)(m0 + lm + 64) * 1024 + k0 + lk8], true);
        #pragma unroll
        for (int p = 0; p < 4; p++)
            cp16(smem_u32(&Bs[(lm + p * 64) * 20 + lw4]),
                 &Bm[(size_t)(n0 + lm + p * 64) * 1024 + k0 + lk8], true);
    };

    cpslab(0, 0); CP_COMMIT();
    for (int s = 0; s < 32; s++) {
        int cur = s & 1;
        if (s < 31) { cpslab(cur ^ 1, (s + 1) * 32); CP_COMMIT(); CP_WAIT1(); }
        else CP_WAIT0();
        __syncthreads();
        const uint32_t* As = AsB + cur * 2560;
        const uint32_t* Bs = BsB + cur * 5120;
        #pragma unroll
        for (int ks = 0; ks < 2; ks++) {
            uint32_t af[4][4], bf[8][2];
            #pragma unroll
            for (int i = 0; i < 4; i++) {
                const uint32_t* p = As + (wm * 64 + i * 16 + g) * 20 + ks * 8 + r;
                af[i][0] = p[0]; af[i][1] = p[160]; af[i][2] = p[4]; af[i][3] = p[164];
            }
            #pragma unroll
            for (int j = 0; j < 8; j++) {
                const uint32_t* p = Bs + (wn * 64 + j * 8 + g) * 20 + ks * 8 + r;
                bf[j][0] = p[0]; bf[j][1] = p[4];
            }
            #pragma unroll
            for (int i = 0; i < 4; i++)
                #pragma unroll
                for (int j = 0; j < 8; j++)
                    mma16(acc[i][j], af[i], bf[j]);
        }
        __syncthreads();
    }

    #pragma unroll
    for (int i = 0; i < 4; i++) {
        int row0 = m0 + wm * 64 + i * 16 + g;
        #pragma unroll
        for (int j = 0; j < 8; j++) {
            int col = n0 + wn * 64 + j * 8 + r * 2;
            *(float2*)&C[(size_t)row0 * 1024 + col]       = make_float2(acc[i][j][0], acc[i][j][1]);
            *(float2*)&C[(size_t)(row0 + 8) * 1024 + col] = make_float2(acc[i][j][2], acc[i][j][3]);
        }
    }
}

// ---------------- prep ----------------
__global__ void wo_permute(const float* __restrict__ Wo)
{
    int n = blockIdx.x;
    for (int f = threadIdx.x; f < 1024; f += 256) {
        int h = f >> 7, d = f & 127;
        g_Wop[n * 1024 + f] = __float2half(Wo[n * 1024 + d * 8 + h]);
    }
}
__global__ void rel2h(const float* __restrict__ rel)
{
    int i = blockIdx.x * 256 + threadIdx.x;
    if (i < NH * RR * HD) g_relh[i] = __float2half(rel[i]);
}

// ---------------- Qrel (R13-best exact) ----------------
__global__ __launch_bounds__(256) void tc_qrel()
{
    extern __shared__ uint32_t sm[];
    uint32_t* AsB = sm;
    uint32_t* BsB = sm + 7680;
    const int tid = threadIdx.x, lane = tid & 31, wid = tid >> 5;
    const int wm = wid >> 2, wn = wid & 3, g = lane >> 2, r = lane & 3;
    const int r0 = blockIdx.x * 128, q0 = blockIdx.y * 128, bh = blockIdx.z;
    const int h = bh & 7;
    const __half* Aq = g_Qp + (size_t)bh * S_ * HD;
    const __half* Br = g_relh + (size_t)h * RR * HD;
    const int lm = tid >> 2, lk8 = (tid & 3) * 8, lw4 = (tid & 3) * 4;
    const uint32_t as0 = smem_u32(AsB), bs0 = smem_u32(BsB);
    const uint32_t aoff = wm * 5120 + a_lane_off(lane);
    const uint32_t boff = wn * 2560 + b_lane_off(lane);

    float acc[4][4][4];
    #pragma unroll
    for (int i = 0; i < 4; i++) for (int j = 0; j < 4; j++) for (int e = 0; e < 4; e++) acc[i][j][e] = 0.f;

    auto cpslab = [&](int buf, int k0) {
        uint32_t* As = AsB + buf * 2560;
        uint32_t* Bs = BsB + buf * 2560;
        cp16(smem_u32(&As[lm * 20 + lw4]),        &Aq[(size_t)(q0 + lm) * HD + k0 + lk8], true);
        cp16(smem_u32(&As[(lm + 64) * 20 + lw4]), &Aq[(size_t)(q0 + lm + 64) * HD + k0 + lk8], true);
        #pragma unroll
        for (int p = 0; p < 2; p++) {
            int rg = r0 + lm + p * 64;
            cp16(smem_u32(&Bs[(lm + p * 64) * 20 + lw4]),
                 &Br[(size_t)rg * HD + k0 + lk8], true);
        }
    };

    cpslab(0, 0); CP_COMMIT();
    cpslab(1, 32); CP_COMMIT();
    for (int s = 0; s < 4; s++) {
        if (s == 3) CP_WAIT0(); else CP_WAIT1();
        __syncthreads();
        if (s < 2) { cpslab((s + 2) % 3, (s + 2) * 32); CP_COMMIT(); }
        int cur = s % 3;
        slab_att(as0 + cur * 10240 + aoff, bs0 + cur * 10240 + boff, acc);
    }

    #pragma unroll
    for (int i = 0; i < 4; i++) {
        int row0 = q0 + wm * 64 + i * 16 + g;
        #pragma unroll
        for (int j = 0; j < 4; j++) {
            int col = r0 + wn * 32 + j * 8 + r * 2;
            #pragma unroll
            for (int half = 0; half < 2; half++) {
                size_t base = ((size_t)bh * S_ + row0 + half * 8) * RR;
                g_Qrel[base + col]     = __float2half(acc[i][j][half * 2]);
                g_Qrel[base + col + 1] = __float2half(acc[i][j][half * 2 + 1]);
            }
        }
    }
}

// ---------------- Qrel column 256 ----------------
__global__ __launch_bounds__(256) void qrel_last()
{
    int q  = blockIdx.x * 256 + threadIdx.x;
    int bh = blockIdx.y;
    int h  = bh & 7;
    const uint4* qp = (const uint4*)&g_Qp[((size_t)bh * S_ + q) * HD];
    const uint4* rl = (const uint4*)&g_relh[((size_t)h * RR + 256) * HD];
    float sum = 0.f;
    #pragma unroll
    for (int i = 0; i < 16; i++) {
        uint4 a = qp[i], b = rl[i];
        const __half2* ah = (const __half2*)&a;
        const __half2* bh2 = (const __half2*)&b;
        #pragma unroll
        for (int e = 0; e < 4; e++) {
            float2 fa = __half22float2(ah[e]);
            float2 fb = __half22float2(bh2[e]);
            sum += fa.x * fb.x + fa.y * fb.y;
        }
    }
    g_Qrel[((size_t)bh * S_ + q) * RR + 256] = __float2half(sum);
}

// ---------------- banded scores -> fp16 partial probabilities + stats ----------------
__global__ __launch_bounds__(256) void tc_score(const unsigned char* __restrict__ pad)
{
    __shared__ uint32_t As[2][2560], Bs[2][2560];
    __shared__ float sred[512];
    const int tid = threadIdx.x, lane = tid & 31, wid = tid >> 5;
    const int wm = wid >> 2, wn = wid & 3, g = lane >> 2, r = lane & 3;
    const int kt0 = blockIdx.x * 128, q0 = blockIdx.y * 128, bh = blockIdx.z;
    const int b = bh >> 3;
    const int kbase = q0 - RADIUS_;

    // early exit: entire k-tile outside [0, S): P = 0, stats (-inf, 0)
    if (kbase + kt0 + 127 < 0 || kbase + kt0 >= S_) {
        uint4 zero = make_uint4(0u, 0u, 0u, 0u);
        #pragma unroll
        for (int p = 0; p < 8; p++) {
            int idx = tid + p * 256;
            int row = idx >> 4, c8 = (idx & 15) * 8;
            *(uint4*)&g_S[((size_t)bh * S_ + q0 + row) * BAND + kt0 + c8] = zero;
        }
        if (tid < 128)
            g_part[((size_t)bh * S_ + q0 + tid) * 5 + blockIdx.x] =
                make_float2(-INFINITY, 0.f);
        return;
    }

    const __half* Aq = g_Qp + (size_t)bh * S_ * HD;
    const __half* Kb = g_Kp + (size_t)bh * S_ * HD;
    const int lm = tid >> 2, lk8 = (tid & 3) * 8, lw4 = (tid & 3) * 4;

    float acc[4][4][4];
    #pragma unroll
    for (int i = 0; i < 4; i++) for (int j = 0; j < 4; j++) for (int e = 0; e < 4; e++) acc[i][j][e] = 0.f;

    auto cpslab = [&](int buf, int k0) {
        cp16(smem_u32(&As[buf][lm * 20 + lw4]),        &Aq[(size_t)(q0 + lm) * HD + k0 + lk8], true);
        cp16(smem_u32(&As[buf][(lm + 64) * 20 + lw4]), &Aq[(size_t)(q0 + lm + 64) * HD + k0 + lk8], true);
        #pragma unroll
        for (int p = 0; p < 2; p++) {
            int k = kbase + kt0 + lm + p * 64;
            int kc = k < 0 ? 0 : (k >= S_ ? S_ - 1 : k);
            cp16(smem_u32(&Bs[buf][(lm + p * 64) * 20 + lw4]),
                 &Kb[(size_t)kc * HD + k0 + lk8], k >= 0 && k < S_);
        }
    };

    cpslab(0, 0); CP_COMMIT();
    for (int s = 0; s < 4; s++) {
        int cur = s & 1;
        if (s < 3) { cpslab(cur ^ 1, (s + 1) * 32); CP_COMMIT(); CP_WAIT1(); }
        else CP_WAIT0();
        __syncthreads();
        mma_slab16(As[cur], Bs[cur], wm, wn, g, r, acc);
        __syncthreads();
    }

    bool okcol[8];
    int  kk_arr[8];
    #pragma unroll
    for (int j = 0; j < 4; j++)
        #pragma unroll
        for (int e = 0; e < 2; e++) {
            int kk = kt0 + wn * 32 + j * 8 + r * 2 + e;
            int k = kbase + kk;
            kk_arr[j * 2 + e] = kk;
            okcol[j * 2 + e] = (k >= 0) && (k < S_) && (pad[b * S_ + (k & 1023)] == 0);
        }

    // masked energies in acc (no store yet)
    const float scale = 0.08838834764831845f;
    #pragma unroll
    for (int i = 0; i < 4; i++) {
        #pragma unroll
        for (int half = 0; half < 2; half++) {
            int qg = q0 + wm * 64 + i * 16 + g + half * 8;
            size_t qrow = (size_t)bh * S_ + qg;
            const __half* qr = &g_Qrel[qrow * RR];
            #pragma unroll
            for (int j = 0; j < 4; j++) {
                #pragma unroll
                for (int e = 0; e < 2; e++) {
                    int kk = kk_arr[j * 2 + e];
                    int k = kbase + kk;
                    int dlt = k - qg;
                    float val = -INFINITY;
                    if (okcol[j * 2 + e] && dlt >= -RADIUS_ && dlt <= RADIUS_) {
                        int rid = dlt < -MAXDIST ? -MAXDIST : (dlt > MAXDIST ? MAXDIST : dlt);
                        rid += MAXDIST;
                        val = (acc[i][j][half * 2 + e] + __half2float(qr[rid])) * scale;
                    }
                    acc[i][j][half * 2 + e] = val;
                }
            }
        }
    }

    // tile max per row
    #pragma unroll
    for (int i = 0; i < 4; i++)
        #pragma unroll
        for (int half = 0; half < 2; half++) {
            int rloc = wm * 64 + i * 16 + g + half * 8;
            float tm = -INFINITY;
            #pragma unroll
            for (int j = 0; j < 4; j++) {
                tm = fmaxf(tm, acc[i][j][half * 2]);
                tm = fmaxf(tm, acc[i][j][half * 2 + 1]);
            }
            tm = fmaxf(tm, __shfl_xor_sync(0xffffffffu, tm, 1));
            tm = fmaxf(tm, __shfl_xor_sync(0xffffffffu, tm, 2));
            if (r == 0) sred[rloc * 4 + wn] = tm;
        }
    __syncthreads();
    float Mt[4][2];
    #pragma unroll
    for (int i = 0; i < 4; i++)
        #pragma unroll
        for (int half = 0; half < 2; half++) {
            int rloc = wm * 64 + i * 16 + g + half * 8;
            Mt[i][half] = fmaxf(fmaxf(sred[rloc * 4], sred[rloc * 4 + 1]),
                                fmaxf(sred[rloc * 4 + 2], sred[rloc * 4 + 3]));
        }
    __syncthreads();
    // exp + store fp16 P + tile sum
    #pragma unroll
    for (int i = 0; i < 4; i++)
        #pragma unroll
        for (int half = 0; half < 2; half++) {
            int rloc = wm * 64 + i * 16 + g + half * 8;
            size_t qrow = (size_t)bh * S_ + q0 + rloc;
            float ts = 0.f;
            #pragma unroll
            for (int j = 0; j < 4; j++) {
                float pe0 = fexp(acc[i][j][half * 2]     - Mt[i][half]);
                float pe1 = fexp(acc[i][j][half * 2 + 1] - Mt[i][half]);
                ts += pe0 + pe1;
                *(uint32_t*)&g_S[qrow * BAND + kk_arr[j * 2]] = f2h2(pe0, pe1);
            }
            ts += __shfl_xor_sync(0xffffffffu, ts, 1);
            ts += __shfl_xor_sync(0xffffffffu, ts, 2);
            if (r == 0) sred[rloc * 4 + wn] = ts;
        }
    __syncthreads();
    if (wn == 0 && r == 0) {
        #pragma unroll
        for (int i = 0; i < 4; i++)
            #pragma unroll
            for (int half = 0; half < 2; half++) {
                int rloc = wm * 64 + i * 16 + g + half * 8;
                float Ssum = sred[rloc * 4] + sred[rloc * 4 + 1] +
                             sred[rloc * 4 + 2] + sred[rloc * 4 + 3];
                g_part[((size_t)bh * S_ + q0 + rloc) * 5 + blockIdx.x] =
                    make_float2(Mt[i][half], Ssum);
            }
    }
}

// ---------------- PV: fp16 partial P * per-tile factor ----------------
__global__ __launch_bounds__(256) void tc_pv()
{
    __shared__ uint32_t As[2][2560], Bs[2][2560];
    __shared__ float sF[640];     // [row 0..127][tile 0..4] factor = exp(Mt - M)/Ssum
    const int tid = threadIdx.x, lane = tid & 31, wid = tid >> 5;
    const int wm = wid >> 2, wn = wid & 3, g = lane >> 2, r = lane & 3;
    const int q0 = blockIdx.x * 128, bh = blockIdx.y;
    const int b = bh >> 3, h = bh & 7;
    const int kbase = q0 - RADIUS_;
    const __half* Vb = g_Vp + (size_t)bh * S_ * HD;
    const __half* Sbase = g_S + ((size_t)bh * S_ + q0) * BAND;
    const int lm = tid >> 2, lk8 = (tid & 3) * 8, lw4 = (tid & 3) * 4;
    const int vk2 = (lane & 15) * 2;
    const int vd  = wid * 16 + (lane >> 4) * 4;

    if (tid < 128) {
        const float2* pp = &g_part[((size_t)bh * S_ + q0 + tid) * 5];
        float2 p0 = pp[0], p1 = pp[1], p2 = pp[2], p3 = pp[3], p4 = pp[4];
        float M = fmaxf(fmaxf(fmaxf(p0.x, p1.x), fmaxf(p2.x, p3.x)), p4.x);
        float e0 = fexp(p0.x - M), e1 = fexp(p1.x - M), e2 = fexp(p2.x - M),
              e3 = fexp(p3.x - M), e4 = fexp(p4.x - M);
        float inv = 1.f / (p0.y * e0 + p1.y * e1 + p2.y * e2 + p3.y * e3 + p4.y * e4);
        sF[tid * 5 + 0] = e0 * inv;
        sF[tid * 5 + 1] = e1 * inv;
        sF[tid * 5 + 2] = e2 * inv;
        sF[tid * 5 + 3] = e3 * inv;
        sF[tid * 5 + 4] = e4 * inv;
    }
    __syncthreads();

    float acc[4][4][4];
    #pragma unroll
    for (int i = 0; i < 4; i++) for (int j = 0; j < 4; j++) for (int e = 0; e < 4; e++) acc[i][j][e] = 0.f;

    uint4 pa0, pa1;
    uint2 pe0, pe1, po0, po1;
    auto ldg = [&](int k0) {
        pa0 = *(const uint4*)&Sbase[(size_t)lm * BAND + k0 + lk8];
        pa1 = *(const uint4*)&Sbase[(size_t)(lm + 64) * BAND + k0 + lk8];
        int ke = kbase + k0 + vk2;
        int ko = ke + 1;
        bool oke = (ke >= 0 && ke < S_);
        bool oko = (ko >= 0 && ko < S_);
        pe0 = oke ? *(const uint2*)&Vb[(size_t)ke * HD + vd]     : make_uint2(0u, 0u);
        pe1 = oke ? *(const uint2*)&Vb[(size_t)ke * HD + vd + 8] : make_uint2(0u, 0u);
        po0 = oko ? *(const uint2*)&Vb[(size_t)ko * HD + vd]     : make_uint2(0u, 0u);
        po1 = oko ? *(const uint2*)&Vb[(size_t)ko * HD + vd + 8] : make_uint2(0u, 0u);
    };
    auto sts = [&](int buf, int t) {
        float f0 = sF[lm * 5 + t];
        float f1 = sF[(lm + 64) * 5 + t];
        const __half2* h0 = (const __half2*)&pa0;
        const __half2* h1 = (const __half2*)&pa1;
        uint4 u0, u1;
        float2 v;
        v = __half22float2(h0[0]); u0.x = f2h2(v.x * f0, v.y * f0);
        v = __half22float2(h0[1]); u0.y = f2h2(v.x * f0, v.y * f0);
        v = __half22float2(h0[2]); u0.z = f2h2(v.x * f0, v.y * f0);
        v = __half22float2(h0[3]); u0.w = f2h2(v.x * f0, v.y * f0);
        v = __half22float2(h1[0]); u1.x = f2h2(v.x * f1, v.y * f1);
        v = __half22float2(h1[1]); u1.y = f2h2(v.x * f1, v.y * f1);
        v = __half22float2(h1[2]); u1.z = f2h2(v.x * f1, v.y * f1);
        v = __half22float2(h1[3]); u1.w = f2h2(v.x * f1, v.y * f1);
        *(uint4*)&As[buf][lm * 20 + lw4]        = u0;
        *(uint4*)&As[buf][(lm + 64) * 20 + lw4] = u1;
        int wkk = lane & 15;
        const __half* he0 = (const __half*)&pe0;
        const __half* he1 = (const __half*)&pe1;
        const __half* ho0 = (const __half*)&po0;
        const __half* ho1 = (const __half*)&po1;
        #pragma unroll
        for (int dd = 0; dd < 4; dd++) {
            __half2 w0 = __halves2half2(he0[dd], ho0[dd]);
            __half2 w1 = __halves2half2(he1[dd], ho1[dd]);
            Bs[buf][(vd + dd) * 20 + wkk]     = *(uint32_t*)&w0;
            Bs[buf][(vd + 8 + dd) * 20 + wkk] = *(uint32_t*)&w1;
        }
    };

    ldg(0); sts(0, 0); __syncthreads();
    for (int s = 0; s < 20; s++) {
        int cur = s & 1;
        if (s < 19) ldg((s + 1) * 32);
        mma_slab16(As[cur], Bs[cur], wm, wn, g, r, acc);
        if (s < 19) sts(cur ^ 1, (s + 1) >> 2);
        __syncthreads();
    }

    #pragma unroll
    for (int i = 0; i < 4; i++) {
        #pragma unroll
        for (int half = 0; half < 2; half++) {
            int q = q0 + wm * 64 + i * 16 + g + half * 8;
            size_t base = ((size_t)(b * S_ + q)) * EMBED + h * HD;
            #pragma unroll
            for (int j = 0; j < 4; j++) {
                int d = wn * 32 + j * 8 + r * 2;
                *(uint32_t*)&g_ctx[base + d] =
                    f2h2(acc[i][j][half * 2], acc[i][j][half * 2 + 1]);
            }
        }
    }
}

// ---------------- launcher ----------------
extern "C" void kernel_launch(void* const* d_in, const int* in_sizes, int n_in,
                              void* d_out, int out_size)
{
    const float*         Q   = (const float*)d_in[0];
    const float*         K   = (const float*)d_in[1];
    const float*         V   = (const float*)d_in[2];
    const unsigned char* pad = (const unsigned char*)d_in[4];
    const float*         Wq  = (const float*)d_in[5];
    const float*         Wk  = (const float*)d_in[6];
    const float*         Wv  = (const float*)d_in[7];
    const float*         Wo  = (const float*)d_in[8];
    const float*         rel = (const float*)d_in[9];
    float*               out = (float*)d_out;

    __half *Qp, *Kp, *Vp, *ctx, *Wop;
    cudaGetSymbolAddress((void**)&Qp,  g_Qp);
    cudaGetSymbolAddress((void**)&Kp,  g_Kp);
    cudaGetSymbolAddress((void**)&Vp,  g_Vp);
    cudaGetSymbolAddress((void**)&ctx, g_ctx);
    cudaGetSymbolAddress((void**)&Wop, g_Wop);

    const int SMEM_W  = (2560 + 5120) * 2 * 4;
    const int SMEM_A3 = (2560 + 2560) * 3 * 4;
    cudaFuncSetAttribute(proj3_gemm, cudaFuncAttributeMaxDynamicSharedMemorySize, SMEM_W);
    cudaFuncSetAttribute(out_gemm,   cudaFuncAttributeMaxDynamicSharedMemorySize, SMEM_W);
    cudaFuncSetAttribute(tc_qrel,    cudaFuncAttributeMaxDynamicSharedMemorySize, SMEM_A3);

    proj3_gemm<<<dim3(4, 32, 3), 256, SMEM_W>>>(Q, K, V, Wq, Wk, Wv, Qp, Kp, Vp);
    wo_permute<<<1024, 256>>>(Wo);
    rel2h<<<(NH * RR * HD + 255) / 256, 256>>>(rel);

    tc_qrel<<<dim3(2, 8, 32), 256, SMEM_A3>>>();
    qrel_last<<<dim3(4, 32), 256>>>();
    tc_score<<<dim3(5, 8, 32), 256>>>(pad);
    tc_pv<<<dim3(8, 32), 256>>>();

    out_gemm<<<dim3(4, 32), 256, SMEM_W>>>(ctx, Wop, out);
}